// round 1
// baseline (speedup 1.0000x reference)
#include <cuda_runtime.h>

// DNGPU recurrence: 128 sequential steps of
//   reset = sigmoid(conv3(mem, w_r) + b_r)
//   gate  = sigmoid(conv3(mem, w_g) + b_g)
//   cand  = tanh(conv3(reset*mem, w_c) + b_c)
//   mem   = gate * shift_right(mem) + (1-gate) * cand
// B=32, L=128, C=192, K=3.  One kernel launch per step (graph-captured),
// one CTA per (batch, 32-row L-chunk), halo recompute of reset/gate for
// the +-1 boundary rows so no intra-step global sync is needed.
// Inner loops use packed fma.rn.f32x2 (sm_100 fp32 peak requires it).

#define NB 32
#define NL 128
#define NC 192
#define TL 32
#define SM_MEM_ROWS 38   // rows l0-2 .. l0+33 (+2 pad rows, zero-filled)
#define SM_TMP_ROWS 34   // reset*mem rows l0-1 .. l0+32
#define SM_GATE_ROWS 32
#define SMEM_FLOATS ((SM_MEM_ROWS + SM_TMP_ROWS + SM_GATE_ROWS) * NC)
#define SMEM_BYTES (SMEM_FLOATS * 4)

__device__ float g_buf0[NB * NL * NC];
__device__ float g_buf1[NB * NL * NC];

__device__ __forceinline__ unsigned long long pk2(float a, float b) {
    unsigned long long r;
    asm("mov.b64 %0, {%1,%2};" : "=l"(r) : "f"(a), "f"(b));
    return r;
}
__device__ __forceinline__ void upk2(unsigned long long v, float& a, float& b) {
    asm("mov.b64 {%0,%1}, %2;" : "=f"(a), "=f"(b) : "l"(v));
}
__device__ __forceinline__ void fma2(unsigned long long& d, unsigned long long a,
                                     unsigned long long b) {
    asm("fma.rn.f32x2 %0, %1, %2, %0;" : "+l"(d) : "l"(a), "l"(b));
}
__device__ __forceinline__ float sigm(float x) {
    return 1.0f / (1.0f + expf(-x));
}

__global__ void __launch_bounds__(256, 1)
dngpu_step(const float* __restrict__ gin, float* __restrict__ gout,
           const float* __restrict__ wr, const float* __restrict__ br,
           const float* __restrict__ wg, const float* __restrict__ bg,
           const float* __restrict__ wc, const float* __restrict__ bc) {
    extern __shared__ float sm[];
    float* s_mem  = sm;                          // [38][192]
    float* s_tmp  = sm + SM_MEM_ROWS * NC;       // [34][192]  reset*mem
    float* s_gate = s_tmp + SM_TMP_ROWS * NC;    // [32][192]

    const int b  = blockIdx.y;
    const int l0 = blockIdx.x * TL;
    const int tx = threadIdx.x;
    const float* gmb = gin + (size_t)b * NL * NC;

    // ---- load mem tile rows (l0-2 .. l0+33), zero outside [0, NL) and pad rows
    for (int t = tx; t < SM_MEM_ROWS * (NC / 4); t += 256) {
        int rr = t / (NC / 4);
        int c4 = (t % (NC / 4)) * 4;
        int ab = l0 - 2 + rr;
        float4 v = make_float4(0.f, 0.f, 0.f, 0.f);
        if (rr < 36 && ab >= 0 && ab < NL)
            v = *(const float4*)(gmb + ab * NC + c4);
        *(float4*)(s_mem + rr * NC + c4) = v;
    }
    __syncthreads();

    // ---- Phase 1: rg-conv over 34 rows (r = 0..33 ~ abs l0-1 .. l0+32),
    //      384 output channels (0..191 reset, 192..383 gate).
    {
        const int cog = tx & 63;          // 64 channel groups of 6
        const int rg0 = (tx >> 6) * 9;    // row groups: 0,9,18,27 (9 rows each)
        const int co6 = cog * 6;
        const bool isR = (co6 < NC);
        const float* wb = isR ? wr : wg;
        const float* bb = isR ? br : bg;
        const int coo = isR ? co6 : (co6 - NC);

        unsigned long long acc[9][3];
        {
            unsigned long long c0 = pk2(bb[coo + 0], bb[coo + 1]);
            unsigned long long c1 = pk2(bb[coo + 2], bb[coo + 3]);
            unsigned long long c2 = pk2(bb[coo + 4], bb[coo + 5]);
#pragma unroll
            for (int i = 0; i < 9; i++) {
                acc[i][0] = c0; acc[i][1] = c1; acc[i][2] = c2;
            }
        }

#pragma unroll 1
        for (int k = 0; k < 3; k++) {
            const float* wk = wb + k * NC * NC + coo;
            const float* xb = s_mem + (rg0 + k) * NC;
#pragma unroll 2
            for (int ci4 = 0; ci4 < NC / 4; ci4++) {
                const int ci = ci4 * 4;
                float4 xv[9];
#pragma unroll
                for (int i = 0; i < 9; i++)
                    xv[i] = *(const float4*)(xb + i * NC + ci);
#pragma unroll
                for (int c = 0; c < 4; c++) {
                    const unsigned long long* wp =
                        (const unsigned long long*)(wk + (ci + c) * NC);
                    unsigned long long w0 = wp[0], w1 = wp[1], w2 = wp[2];
#pragma unroll
                    for (int i = 0; i < 9; i++) {
                        float xc = ((const float*)&xv[i])[c];
                        unsigned long long x2 = pk2(xc, xc);
                        fma2(acc[i][0], x2, w0);
                        fma2(acc[i][1], x2, w1);
                        fma2(acc[i][2], x2, w2);
                    }
                }
            }
        }

#pragma unroll
        for (int i = 0; i < 9; i++) {
            int r = rg0 + i;
            if (r < 34) {
#pragma unroll
                for (int p = 0; p < 3; p++) {
                    float z0, z1;
                    upk2(acc[i][p], z0, z1);
                    int co = coo + 2 * p;
                    float s0 = sigm(z0);
                    float s1 = sigm(z1);
                    if (isR) {
                        s_tmp[r * NC + co]     = s0 * s_mem[(r + 1) * NC + co];
                        s_tmp[r * NC + co + 1] = s1 * s_mem[(r + 1) * NC + co + 1];
                    } else if (r >= 1 && r <= 32) {
                        s_gate[(r - 1) * NC + co]     = s0;
                        s_gate[(r - 1) * NC + co + 1] = s1;
                    }
                }
            }
        }
    }
    __syncthreads();

    // ---- Phase 2: cand-conv over own 32 rows from s_tmp, then gated update
    {
        const int cog = tx & 31;          // 32 channel groups of 6
        const int co6 = cog * 6;
        const int jg = (tx >> 5) * 4;     // row groups: 0,4,...,28 (4 rows each)

        unsigned long long acc[4][3];
        {
            unsigned long long c0 = pk2(bc[co6 + 0], bc[co6 + 1]);
            unsigned long long c1 = pk2(bc[co6 + 2], bc[co6 + 3]);
            unsigned long long c2 = pk2(bc[co6 + 4], bc[co6 + 5]);
#pragma unroll
            for (int i = 0; i < 4; i++) {
                acc[i][0] = c0; acc[i][1] = c1; acc[i][2] = c2;
            }
        }

#pragma unroll 1
        for (int k = 0; k < 3; k++) {
            const float* wk = wc + k * NC * NC + co6;
            const float* xb = s_tmp + (jg + k) * NC;
#pragma unroll 2
            for (int ci4 = 0; ci4 < NC / 4; ci4++) {
                const int ci = ci4 * 4;
                float4 xv[4];
#pragma unroll
                for (int i = 0; i < 4; i++)
                    xv[i] = *(const float4*)(xb + i * NC + ci);
#pragma unroll
                for (int c = 0; c < 4; c++) {
                    const unsigned long long* wp =
                        (const unsigned long long*)(wk + (ci + c) * NC);
                    unsigned long long w0 = wp[0], w1 = wp[1], w2 = wp[2];
#pragma unroll
                    for (int i = 0; i < 4; i++) {
                        float xc = ((const float*)&xv[i])[c];
                        unsigned long long x2 = pk2(xc, xc);
                        fma2(acc[i][0], x2, w0);
                        fma2(acc[i][1], x2, w1);
                        fma2(acc[i][2], x2, w2);
                    }
                }
            }
        }

#pragma unroll
        for (int i = 0; i < 4; i++) {
            int j = jg + i;
            float* orow = gout + ((size_t)b * NL + l0 + j) * NC;
#pragma unroll
            for (int p = 0; p < 3; p++) {
                float z0, z1;
                upk2(acc[i][p], z0, z1);
                int co = co6 + 2 * p;
                float c0 = tanhf(z0);
                float c1 = tanhf(z1);
                float g0 = s_gate[j * NC + co];
                float g1 = s_gate[j * NC + co + 1];
                float sh0 = s_mem[(j + 1) * NC + co];
                float sh1 = s_mem[(j + 1) * NC + co + 1];
                orow[co]     = g0 * sh0 + (1.0f - g0) * c0;
                orow[co + 1] = g1 * sh1 + (1.0f - g1) * c1;
            }
        }
    }
}

extern "C" void kernel_launch(void* const* d_in, const int* in_sizes, int n_in,
                              void* d_out, int out_size) {
    const float* x  = (const float*)d_in[0];
    const float* wr = (const float*)d_in[1];
    const float* br = (const float*)d_in[2];
    const float* wg = (const float*)d_in[3];
    const float* bg = (const float*)d_in[4];
    const float* wc = (const float*)d_in[5];
    const float* bc = (const float*)d_in[6];
    float* out = (float*)d_out;

    float *b0, *b1;
    cudaGetSymbolAddress((void**)&b0, g_buf0);
    cudaGetSymbolAddress((void**)&b1, g_buf1);

    cudaFuncSetAttribute(dngpu_step, cudaFuncAttributeMaxDynamicSharedMemorySize,
                         SMEM_BYTES);

    dim3 grid(NL / TL, NB);
    for (int s = 0; s < NL; s++) {
        const float* src = (s == 0) ? x : ((s & 1) ? b0 : b1);
        float* dst = (s == NL - 1) ? out : ((s & 1) ? b1 : b0);
        dngpu_step<<<grid, 256, SMEM_BYTES>>>(src, dst, wr, br, wg, bg, wc, bc);
    }
}

// round 2
// speedup vs baseline: 1.0469x; 1.0469x over previous
#include <cuda_runtime.h>

// DNGPU recurrence, round 2: 512-thread CTAs (16 warps/SM) to fix the
// latency-bound 12.5%-occupancy profile of round 1. Same algorithm:
// one launch per step, halo recompute of reset/gate, f32x2 packed FMAs.

#define NB 32
#define NL 128
#define NC 192
#define TL 32
#define NTHREADS 512
#define SM_MEM_ROWS 38   // rows l0-2 .. l0+33 (+2 pad rows, zero-filled)
#define SM_TMP_ROWS 34   // reset*mem rows l0-1 .. l0+32
#define SM_GATE_ROWS 32
#define SMEM_FLOATS ((SM_MEM_ROWS + SM_TMP_ROWS + SM_GATE_ROWS) * NC)
#define SMEM_BYTES (SMEM_FLOATS * 4)

typedef unsigned long long ull;

__device__ float g_buf0[NB * NL * NC];
__device__ float g_buf1[NB * NL * NC];

__device__ __forceinline__ ull pk2(float a, float b) {
    ull r;
    asm("mov.b64 %0, {%1,%2};" : "=l"(r) : "f"(a), "f"(b));
    return r;
}
__device__ __forceinline__ void upk2(ull v, float& a, float& b) {
    asm("mov.b64 {%0,%1}, %2;" : "=f"(a), "=f"(b) : "l"(v));
}
__device__ __forceinline__ void fma2(ull& d, ull a, ull b) {
    asm("fma.rn.f32x2 %0, %1, %2, %0;" : "+l"(d) : "l"(a), "l"(b));
}
__device__ __forceinline__ float sigm(float x) {
    return 1.0f / (1.0f + expf(-x));
}

// Accumulate a K=3, Cin=192 conv for R consecutive output rows and 6
// consecutive output channels. x0 = smem row base (output row rs reads
// smem rows rs..rs+2). wb = weight base already offset by output channel.
template <int R>
__device__ __forceinline__ void conv_acc(const float* __restrict__ x0,
                                         const float* __restrict__ wb,
                                         ull (&acc)[R][3]) {
#pragma unroll 1
    for (int k = 0; k < 3; k++) {
        const float* wk = wb + k * NC * NC;
        const float* xb = x0 + k * NC;
#pragma unroll 2
        for (int ci4 = 0; ci4 < NC / 4; ci4++) {
            const int ci = ci4 * 4;
            float4 xv[R];
#pragma unroll
            for (int i = 0; i < R; i++)
                xv[i] = *(const float4*)(xb + i * NC + ci);
#pragma unroll
            for (int c = 0; c < 4; c++) {
                const ull* wp = (const ull*)(wk + (ci + c) * NC);
                ull w0 = wp[0], w1 = wp[1], w2 = wp[2];
#pragma unroll
                for (int i = 0; i < R; i++) {
                    float xc = ((const float*)&xv[i])[c];
                    ull x2 = pk2(xc, xc);
                    fma2(acc[i][0], x2, w0);
                    fma2(acc[i][1], x2, w1);
                    fma2(acc[i][2], x2, w2);
                }
            }
        }
    }
}

template <int R>
__device__ __forceinline__ void init_acc(ull (&acc)[R][3],
                                         const float* __restrict__ bb, int coo) {
    ull c0 = pk2(bb[coo + 0], bb[coo + 1]);
    ull c1 = pk2(bb[coo + 2], bb[coo + 3]);
    ull c2 = pk2(bb[coo + 4], bb[coo + 5]);
#pragma unroll
    for (int i = 0; i < R; i++) {
        acc[i][0] = c0; acc[i][1] = c1; acc[i][2] = c2;
    }
}

template <int R>
__device__ __forceinline__ void epi1(ull (&acc)[R][3], int rs, int coo,
                                     bool isR, float* __restrict__ s_tmp,
                                     float* __restrict__ s_gate,
                                     const float* __restrict__ s_mem) {
#pragma unroll
    for (int i = 0; i < R; i++) {
        int r = rs + i;
#pragma unroll
        for (int p = 0; p < 3; p++) {
            float z0, z1;
            upk2(acc[i][p], z0, z1);
            int co = coo + 2 * p;
            float s0 = sigm(z0);
            float s1 = sigm(z1);
            if (isR) {
                s_tmp[r * NC + co]     = s0 * s_mem[(r + 1) * NC + co];
                s_tmp[r * NC + co + 1] = s1 * s_mem[(r + 1) * NC + co + 1];
            } else if (r >= 1 && r <= 32) {
                s_gate[(r - 1) * NC + co]     = s0;
                s_gate[(r - 1) * NC + co + 1] = s1;
            }
        }
    }
}

__global__ void __launch_bounds__(NTHREADS, 1)
dngpu_step(const float* __restrict__ gin, float* __restrict__ gout,
           const float* __restrict__ wr, const float* __restrict__ br,
           const float* __restrict__ wg, const float* __restrict__ bg,
           const float* __restrict__ wc, const float* __restrict__ bc) {
    extern __shared__ float sm[];
    float* s_mem  = sm;                          // [38][192]
    float* s_tmp  = sm + SM_MEM_ROWS * NC;       // [34][192]  reset*mem
    float* s_gate = s_tmp + SM_TMP_ROWS * NC;    // [32][192]

    const int b  = blockIdx.y;
    const int l0 = blockIdx.x * TL;
    const int tx = threadIdx.x;
    const float* gmb = gin + (size_t)b * NL * NC;

    // ---- load mem tile rows (l0-2 .. l0+33), zero outside [0, NL) and pads
    for (int t = tx; t < SM_MEM_ROWS * (NC / 4); t += NTHREADS) {
        int rr = t / (NC / 4);
        int c4 = (t % (NC / 4)) * 4;
        int ab = l0 - 2 + rr;
        float4 v = make_float4(0.f, 0.f, 0.f, 0.f);
        if (rr < 36 && ab >= 0 && ab < NL)
            v = *(const float4*)(gmb + ab * NC + c4);
        *(float4*)(s_mem + rr * NC + c4) = v;
    }
    __syncthreads();

    // ---- Phase 1: reset/gate conv over 34 rows (r=0..33 ~ abs l0-1..l0+32),
    //      384 output channels. 64 channel-groups(6) x 8 row-groups.
    //      Row-group sizes {5,5,4,4,4,4,4,4} cover 34 rows with no waste.
    {
        const int cog = tx & 63;
        const int g   = tx >> 6;
        const int co6 = cog * 6;
        const bool isR = (co6 < NC);
        const float* wb = isR ? wr : wg;
        const float* bb = isR ? br : bg;
        const int coo = isR ? co6 : (co6 - NC);

        if (g < 2) {
            const int rs = g * 5;
            ull acc[5][3];
            init_acc<5>(acc, bb, coo);
            conv_acc<5>(s_mem + rs * NC, wb + coo, acc);
            epi1<5>(acc, rs, coo, isR, s_tmp, s_gate, s_mem);
        } else {
            const int rs = 10 + (g - 2) * 4;
            ull acc[4][3];
            init_acc<4>(acc, bb, coo);
            conv_acc<4>(s_mem + rs * NC, wb + coo, acc);
            epi1<4>(acc, rs, coo, isR, s_tmp, s_gate, s_mem);
        }
    }
    __syncthreads();

    // ---- Phase 2: cand conv over own 32 rows from s_tmp, gated update.
    //      32 channel-groups(6) x 16 row-groups of 2 rows.
    {
        const int cog = tx & 31;
        const int co6 = cog * 6;
        const int jg  = (tx >> 5) * 2;

        ull acc[2][3];
        init_acc<2>(acc, bc, co6);
        conv_acc<2>(s_tmp + jg * NC, wc + co6, acc);

#pragma unroll
        for (int i = 0; i < 2; i++) {
            int j = jg + i;
            float* orow = gout + ((size_t)b * NL + l0 + j) * NC;
#pragma unroll
            for (int p = 0; p < 3; p++) {
                float z0, z1;
                upk2(acc[i][p], z0, z1);
                int co = co6 + 2 * p;
                float c0 = tanhf(z0);
                float c1 = tanhf(z1);
                float g0 = s_gate[j * NC + co];
                float g1 = s_gate[j * NC + co + 1];
                float sh0 = s_mem[(j + 1) * NC + co];
                float sh1 = s_mem[(j + 1) * NC + co + 1];
                orow[co]     = g0 * sh0 + (1.0f - g0) * c0;
                orow[co + 1] = g1 * sh1 + (1.0f - g1) * c1;
            }
        }
    }
}

extern "C" void kernel_launch(void* const* d_in, const int* in_sizes, int n_in,
                              void* d_out, int out_size) {
    const float* x  = (const float*)d_in[0];
    const float* wr = (const float*)d_in[1];
    const float* br = (const float*)d_in[2];
    const float* wg = (const float*)d_in[3];
    const float* bg = (const float*)d_in[4];
    const float* wc = (const float*)d_in[5];
    const float* bc = (const float*)d_in[6];
    float* out = (float*)d_out;

    float *b0, *b1;
    cudaGetSymbolAddress((void**)&b0, g_buf0);
    cudaGetSymbolAddress((void**)&b1, g_buf1);

    cudaFuncSetAttribute(dngpu_step, cudaFuncAttributeMaxDynamicSharedMemorySize,
                         SMEM_BYTES);

    dim3 grid(NL / TL, NB);
    for (int s = 0; s < NL; s++) {
        const float* src = (s == 0) ? x : ((s & 1) ? b0 : b1);
        float* dst = (s == NL - 1) ? out : ((s & 1) ? b1 : b0);
        dngpu_step<<<grid, NTHREADS, SMEM_BYTES>>>(src, dst, wr, br, wg, bg, wc, bc);
    }
}

// round 3
// speedup vs baseline: 1.2866x; 1.2289x over previous
#include <cuda_runtime.h>

// DNGPU recurrence, round 3.
// Fixes from ncu R2: weight LDGs were 6 wavefronts each (stride-24B lanes);
// now pair-interleaved channel mapping -> lanes consecutive 8B -> 2 wf.
// K-split (Cin halves) doubles per-thread row reuse of weights (R ~ 8.5),
// partial sums combined with packed add.rn.f32x2 through shared memory.

#define NB 32
#define NL 128
#define NC 192
#define TL 32
#define NTHREADS 512
#define SM_MEM_ROWS 36   // abs rows l0-2 .. l0+33
#define SM_TMP_ROWS 34   // reset*mem rows (abs l0-1 .. l0+32)
#define SM_GATE_ROWS 32
#define SM_DATA_FLOATS ((SM_MEM_ROWS + SM_TMP_ROWS + SM_GATE_ROWS) * NC)
#define SM_RED_ULL (256 * 27)   // 256 k-split partner threads x 9 rows x 3 pairs
#define SMEM_BYTES (SM_DATA_FLOATS * 4 + SM_RED_ULL * 8)

typedef unsigned long long ull;

__device__ float g_buf0[NB * NL * NC];
__device__ float g_buf1[NB * NL * NC];

__device__ __forceinline__ ull pk2(float a, float b) {
    ull r;
    asm("mov.b64 %0, {%1,%2};" : "=l"(r) : "f"(a), "f"(b));
    return r;
}
__device__ __forceinline__ void upk2(ull v, float& a, float& b) {
    asm("mov.b64 {%0,%1}, %2;" : "=f"(a), "=f"(b) : "l"(v));
}
__device__ __forceinline__ void fma2(ull& d, ull a, ull b) {
    asm("fma.rn.f32x2 %0, %1, %2, %0;" : "+l"(d) : "l"(a), "l"(b));
}
__device__ __forceinline__ ull add2(ull a, ull b) {
    ull r;
    asm("add.rn.f32x2 %0, %1, %2;" : "=l"(r) : "l"(a), "l"(b));
    return r;
}
__device__ __forceinline__ float sigm(float x) {
    return 1.0f / (1.0f + expf(-x));
}

// K=3 conv partial sum over ci in [ci0, ci0+96), R rows, 3 channel-pairs.
// x0: smem base of first input row (output row rs reads rows rs..rs+2),
//     warp-uniform address -> LDS broadcasts (1 wf).
// w0/w1/w2: weight base already offset by output channel (2 floats used).
template <int R>
__device__ __forceinline__ void conv3(const float* __restrict__ x0,
                                      const float* __restrict__ w0,
                                      const float* __restrict__ w1,
                                      const float* __restrict__ w2,
                                      int ci0, ull (&acc)[R][3]) {
#pragma unroll 1
    for (int k = 0; k < 3; k++) {
        const float* xb  = x0 + k * NC + ci0;
        const float* wk0 = w0 + k * NC * NC + ci0 * NC;
        const float* wk1 = w1 + k * NC * NC + ci0 * NC;
        const float* wk2 = w2 + k * NC * NC + ci0 * NC;
#pragma unroll 1
        for (int ci4 = 0; ci4 < 24; ci4++) {
            float4 xv[R];
#pragma unroll
            for (int i = 0; i < R; i++)
                xv[i] = *(const float4*)(xb + i * NC + ci4 * 4);
#pragma unroll
            for (int c = 0; c < 4; c++) {
                const int woff = (ci4 * 4 + c) * NC;
                ull wa = *(const ull*)(wk0 + woff);
                ull wb = *(const ull*)(wk1 + woff);
                ull wc = *(const ull*)(wk2 + woff);
#pragma unroll
                for (int i = 0; i < R; i++) {
                    float xc = ((const float*)&xv[i])[c];
                    ull x2 = pk2(xc, xc);
                    fma2(acc[i][0], x2, wa);
                    fma2(acc[i][1], x2, wb);
                    fma2(acc[i][2], x2, wc);
                }
            }
        }
    }
}

// ---- phase 1 worker: R rows starting at rs ----
template <int R>
__device__ __forceinline__ void phase1_work(
    int rs, int cog, int h, const float* __restrict__ s_mem,
    float* __restrict__ s_tmp, float* __restrict__ s_gate,
    ull* __restrict__ s_red, int slot,
    const float* __restrict__ wr, const float* __restrict__ br,
    const float* __restrict__ wg, const float* __restrict__ bg) {
    // channel pairs p = cog + 64*j ; p<96 -> reset pair p, else gate pair p-96
    const float* wp[3];
    const float* bp[3];
    int chs[3];
    bool isr[3];
#pragma unroll
    for (int j = 0; j < 3; j++) {
        int p = cog + 64 * j;
        bool r = (p < 96);
        int ch = r ? 2 * p : 2 * (p - 96);
        isr[j] = r;
        chs[j] = ch;
        wp[j] = (r ? wr : wg) + ch;
        bp[j] = (r ? br : bg) + ch;
    }

    ull acc[R][3];
#pragma unroll
    for (int i = 0; i < R; i++)
#pragma unroll
        for (int j = 0; j < 3; j++)
            acc[i][j] = (h == 0) ? pk2(bp[j][0], bp[j][1]) : 0ULL;

    conv3<R>(s_mem + rs * NC, wp[0], wp[1], wp[2], h * 96, acc);

    __syncthreads();
    if (h == 1) {
        ull* dst = s_red + (size_t)slot * 27;
#pragma unroll
        for (int i = 0; i < R; i++)
#pragma unroll
            for (int j = 0; j < 3; j++)
                dst[i * 3 + j] = acc[i][j];
    }
    __syncthreads();
    if (h == 0) {
        const ull* src = s_red + (size_t)slot * 27;
#pragma unroll
        for (int i = 0; i < R; i++) {
            int r = rs + i;
#pragma unroll
            for (int j = 0; j < 3; j++) {
                float z0, z1;
                upk2(add2(acc[i][j], src[i * 3 + j]), z0, z1);
                float s0 = sigm(z0);
                float s1 = sigm(z1);
                int ch = chs[j];
                if (isr[j]) {
                    s_tmp[r * NC + ch]     = s0 * s_mem[(r + 1) * NC + ch];
                    s_tmp[r * NC + ch + 1] = s1 * s_mem[(r + 1) * NC + ch + 1];
                } else if (r >= 1 && r <= 32) {
                    s_gate[(r - 1) * NC + ch]     = s0;
                    s_gate[(r - 1) * NC + ch + 1] = s1;
                }
            }
        }
    }
}

__global__ void __launch_bounds__(NTHREADS, 1)
dngpu_step(const float* __restrict__ gin, float* __restrict__ gout,
           const float* __restrict__ wr, const float* __restrict__ br,
           const float* __restrict__ wg, const float* __restrict__ bg,
           const float* __restrict__ wc, const float* __restrict__ bc) {
    extern __shared__ float sm[];
    float* s_mem  = sm;                                 // [36][192]
    float* s_tmp  = sm + SM_MEM_ROWS * NC;              // [34][192]
    float* s_gate = s_tmp + SM_TMP_ROWS * NC;           // [32][192]
    ull*   s_red  = (ull*)(sm + SM_DATA_FLOATS);        // [256][27]

    const int b  = blockIdx.y;
    const int l0 = blockIdx.x * TL;
    const int tx = threadIdx.x;
    const float* gmb = gin + (size_t)b * NL * NC;

    // ---- load mem tile rows (abs l0-2 .. l0+33), zero outside [0, NL)
    for (int t = tx; t < SM_MEM_ROWS * (NC / 4); t += NTHREADS) {
        int rr = t / (NC / 4);
        int c4 = (t % (NC / 4)) * 4;
        int ab = l0 - 2 + rr;
        float4 v = make_float4(0.f, 0.f, 0.f, 0.f);
        if (ab >= 0 && ab < NL)
            v = *(const float4*)(gmb + ab * NC + c4);
        *(float4*)(s_mem + rr * NC + c4) = v;
    }
    __syncthreads();

    // ---- Phase 1: reset/gate conv, 34 rows (r=0..33 ~ abs l0-1..l0+32)
    //      64 ch-groups x 4 row-groups {9,9,8,8} x 2 K-split halves
    {
        const int cog = tx & 63;
        const int g   = (tx >> 6) & 3;
        const int h   = tx >> 8;
        const int slot = g * 64 + cog;
        if (g < 2)
            phase1_work<9>(g * 9, cog, h, s_mem, s_tmp, s_gate, s_red, slot,
                           wr, br, wg, bg);
        else
            phase1_work<8>(18 + (g - 2) * 8, cog, h, s_mem, s_tmp, s_gate,
                           s_red, slot, wr, br, wg, bg);
    }
    __syncthreads();

    // ---- Phase 2: cand conv, 32 own rows.
    //      32 ch-groups x 8 row-groups (R=4) x 2 K-split halves
    {
        const int cog = tx & 31;
        const int g   = (tx >> 5) & 7;
        const int h   = tx >> 8;
        const int slot = g * 32 + cog;
        const int rs = g * 4;

        const float* wp0 = wc + 2 * cog;            // pair p = cog
        const float* wp1 = wc + 2 * (cog + 32);     // pair p = cog+32
        const float* wp2 = wc + 2 * (cog + 64);     // pair p = cog+64

        ull acc[4][3];
#pragma unroll
        for (int i = 0; i < 4; i++) {
            acc[i][0] = (h == 0) ? pk2(bc[2 * cog],      bc[2 * cog + 1])      : 0ULL;
            acc[i][1] = (h == 0) ? pk2(bc[2 * cog + 64], bc[2 * cog + 65])     : 0ULL;
            acc[i][2] = (h == 0) ? pk2(bc[2 * cog + 128], bc[2 * cog + 129])   : 0ULL;
        }

        conv3<4>(s_tmp + rs * NC, wp0, wp1, wp2, h * 96, acc);

        __syncthreads();
        if (h == 1) {
            ull* dst = s_red + (size_t)slot * 27;
#pragma unroll
            for (int i = 0; i < 4; i++)
#pragma unroll
                for (int j = 0; j < 3; j++)
                    dst[i * 3 + j] = acc[i][j];
        }
        __syncthreads();
        if (h == 0) {
            const ull* src = s_red + (size_t)slot * 27;
#pragma unroll
            for (int i = 0; i < 4; i++) {
                int r = rs + i;
                float* orow = gout + ((size_t)b * NL + l0 + r) * NC;
#pragma unroll
                for (int j = 0; j < 3; j++) {
                    float z0, z1;
                    upk2(add2(acc[i][j], src[i * 3 + j]), z0, z1);
                    int ch = 2 * (cog + 32 * j);
                    float c0 = tanhf(z0);
                    float c1 = tanhf(z1);
                    float g0 = s_gate[r * NC + ch];
                    float g1 = s_gate[r * NC + ch + 1];
                    float sh0 = s_mem[(r + 1) * NC + ch];
                    float sh1 = s_mem[(r + 1) * NC + ch + 1];
                    float2 o;
                    o.x = g0 * sh0 + (1.0f - g0) * c0;
                    o.y = g1 * sh1 + (1.0f - g1) * c1;
                    *(float2*)(orow + ch) = o;
                }
            }
        }
    }
}

extern "C" void kernel_launch(void* const* d_in, const int* in_sizes, int n_in,
                              void* d_out, int out_size) {
    const float* x  = (const float*)d_in[0];
    const float* wr = (const float*)d_in[1];
    const float* br = (const float*)d_in[2];
    const float* wg = (const float*)d_in[3];
    const float* bg = (const float*)d_in[4];
    const float* wc = (const float*)d_in[5];
    const float* bc = (const float*)d_in[6];
    float* out = (float*)d_out;

    float *b0, *b1;
    cudaGetSymbolAddress((void**)&b0, g_buf0);
    cudaGetSymbolAddress((void**)&b1, g_buf1);

    cudaFuncSetAttribute(dngpu_step, cudaFuncAttributeMaxDynamicSharedMemorySize,
                         SMEM_BYTES);

    dim3 grid(NL / TL, NB);
    for (int s = 0; s < NL; s++) {
        const float* src = (s == 0) ? x : ((s & 1) ? b0 : b1);
        float* dst = (s == NL - 1) ? out : ((s & 1) ? b1 : b0);
        dngpu_step<<<grid, NTHREADS, SMEM_BYTES>>>(src, dst, wr, br, wg, bg, wc, bc);
    }
}

// round 6
// speedup vs baseline: 1.4431x; 1.1217x over previous
#include <cuda_runtime.h>
#include <cuda_bf16.h>
#include <cstdint>

// DNGPU recurrence, round 6 (round-5 resubmit after broker infra failure).
// Split-bf16 GEMM formulation on mma.sync HMMA (tcgen05 unavailable: the
// harness compiles PTX for target sm_100, which gates all tcgen05/.cta_group
// features; mma.sync/ldmatrix/cp.async are plain sm_80+ PTX).
// conv3(mem) = sum_k shift_k(mem) @ W[k]: A = padded bf16 hi/lo state rows
// (shift = row-pointer offset), K = 3 taps * 192 = 576 per product, three
// products A0B0 + A1B0 + A0B1 give ~2^-18 relative accuracy in fp32 accum.
// rg kernel: 128 CTAs (batch x conv x N-half), M=128 N=96.
// cand kernel: 128 CTAs (batch x M-half x N-half), M=64 N=96.

typedef __nv_bfloat16 bf16;
typedef __nv_bfloat162 bf162;

#define NB 32
#define NL 128
#define NC 192
#define PADL 130
#define KTOT 576
#define NCHUNK 54

__device__ bf16 g_wt[3 * 2 * NC * KTOT];           // [conv][term][co][k*192+ci]
__device__ bf16 g_ma0[NB * PADL * NC], g_ma1[NB * PADL * NC];
__device__ bf16 g_mb0[NB * PADL * NC], g_mb1[NB * PADL * NC];
__device__ bf16 g_t0[NB * PADL * NC], g_t1[NB * PADL * NC];
__device__ float g_gate[NB * NL * NC];

#define CP16(d, s) \
    asm volatile("cp.async.cg.shared.global [%0], [%1], 16;" :: "r"(d), "l"(s))
#define CP_COMMIT() asm volatile("cp.async.commit_group;" ::: "memory")
#define CP_WAIT(n) asm volatile("cp.async.wait_group %0;" :: "n"(n) : "memory")

__device__ __forceinline__ uint32_t smem_u32(const void* p) {
    uint32_t a;
    asm("{ .reg .u64 t; cvta.to.shared.u64 t, %1; cvt.u32.u64 %0, t; }"
        : "=r"(a) : "l"(p));
    return a;
}
__device__ __forceinline__ void ldsm4(uint32_t (&r)[4], uint32_t a) {
    asm volatile("ldmatrix.sync.aligned.m8n8.x4.shared.b16 {%0,%1,%2,%3}, [%4];"
                 : "=r"(r[0]), "=r"(r[1]), "=r"(r[2]), "=r"(r[3]) : "r"(a));
}
__device__ __forceinline__ void mma16816(float (&c)[4], const uint32_t (&a)[4],
                                         uint32_t b0, uint32_t b1) {
    asm volatile(
        "mma.sync.aligned.m16n8k16.row.col.f32.bf16.bf16.f32 "
        "{%0,%1,%2,%3}, {%4,%5,%6,%7}, {%8,%9}, {%0,%1,%2,%3};"
        : "+f"(c[0]), "+f"(c[1]), "+f"(c[2]), "+f"(c[3])
        : "r"(a[0]), "r"(a[1]), "r"(a[2]), "r"(a[3]), "r"(b0), "r"(b1));
}
__device__ __forceinline__ void split2(float v0, float v1, bf162& hp, bf162& lp) {
    bf16 h0 = __float2bfloat16(v0);
    bf16 h1 = __float2bfloat16(v1);
    hp.x = h0; hp.y = h1;
    lp.x = __float2bfloat16(v0 - __bfloat162float(h0));
    lp.y = __float2bfloat16(v1 - __bfloat162float(h1));
}

// M rows x 32 K-cols A tile + 96 x 32 B tile, 64B rows, xor-swizzled units.
__device__ __forceinline__ void copy_chunk(uint32_t dA, uint32_t dB,
                                           const bf16* __restrict__ ap,
                                           const bf16* __restrict__ bp,
                                           int tx, int M) {
    for (int t = tx; t < M * 4; t += 256) {
        int r = t >> 2, u = t & 3;
        CP16(dA + r * 64 + ((u ^ ((r >> 1) & 3)) << 4), ap + r * NC + u * 8);
    }
    for (int t = tx; t < 384; t += 256) {
        int r = t >> 2, u = t & 3;
        CP16(dB + r * 64 + ((u ^ ((r >> 1) & 3)) << 4), bp + r * KTOT + u * 8);
    }
}

// Full K=1728 (3 products x 576) GEMM into register accumulators.
// a0/a1: hi/lo A bases pre-offset to (batch,row0); b0/b1: hi/lo weight bases
// pre-offset to output-channel block (rows = co, 576 cols).
template <int M, int MI>
__device__ __forceinline__ void gemm_run(bf16* As, bf16* Bs,
                                         const bf16* __restrict__ a0,
                                         const bf16* __restrict__ a1,
                                         const bf16* __restrict__ b0,
                                         const bf16* __restrict__ b1,
                                         int tx, float (&acc)[MI][6][4]) {
    const uint32_t sA = smem_u32(As), sB = smem_u32(Bs);
    const int ABYTES = M * 64;
    const int wid = tx >> 5, lane = tx & 31;
    const int mw = wid >> 1, nw = wid & 1;

    copy_chunk(sA, sB, a0, b0, tx, M);   // chunk 0: p=0, kc=0
    CP_COMMIT();

#pragma unroll 1
    for (int q = 0; q < NCHUNK; q++) {
        if (q + 1 < NCHUNK) {
            int qq = q + 1;
            int p = qq / 18, kc = qq % 18, k = kc / 6, ci0 = (kc % 6) * 32;
            const bf16* ap = ((p == 1) ? a1 : a0) + k * NC + ci0;
            const bf16* bp = ((p == 2) ? b1 : b0) + kc * 32;
            copy_chunk(sA + (qq & 1) * ABYTES, sB + (qq & 1) * 6144, ap, bp, tx, M);
            CP_COMMIT();
            CP_WAIT(1);
        } else {
            CP_WAIT(0);
        }
        __syncthreads();
        const uint32_t bA = sA + (q & 1) * ABYTES;
        const uint32_t bB = sB + (q & 1) * 6144;
#pragma unroll
        for (int h = 0; h < 2; h++) {
            uint32_t af[MI][4];
#pragma unroll
            for (int im = 0; im < MI; im++) {
                int row = mw * (16 * MI) + im * 16 + ((lane >> 3) & 1) * 8 + (lane & 7);
                int u = (h << 1) | (lane >> 4);
                ldsm4(af[im], bA + row * 64 + ((u ^ ((row >> 1) & 3)) << 4));
            }
            uint32_t bfm[3][4];
#pragma unroll
            for (int j2 = 0; j2 < 3; j2++) {
                int nrow = nw * 48 + j2 * 16 + ((lane >> 4) << 3) + (lane & 7);
                int u = (h << 1) | ((lane >> 3) & 1);
                ldsm4(bfm[j2], bB + nrow * 64 + ((u ^ ((nrow >> 1) & 3)) << 4));
            }
#pragma unroll
            for (int im = 0; im < MI; im++)
#pragma unroll
                for (int jn = 0; jn < 6; jn++) {
                    int s = (jn & 1) * 2;
                    mma16816(acc[im][jn], af[im], bfm[jn >> 1][s], bfm[jn >> 1][s + 1]);
                }
        }
        __syncthreads();
    }
}

__device__ __forceinline__ float sigm(float x) { return 1.0f / (1.0f + expf(-x)); }

// ---------------- per-step kernels ----------------
__global__ void __launch_bounds__(256, 1)
rg_kernel(const bf16* __restrict__ cur0, const bf16* __restrict__ cur1,
          const float* __restrict__ br, const float* __restrict__ bg) {
    __shared__ bf16 As[2][128 * 32];
    __shared__ bf16 Bs[2][96 * 32];
    const int tx = threadIdx.x, bx = blockIdx.x;
    const int b = bx >> 2, conv = (bx >> 1) & 1, nq = bx & 1;
    const bf16* a0 = cur0 + (size_t)b * PADL * NC;
    const bf16* a1 = cur1 + (size_t)b * PADL * NC;
    const bf16* w0 = g_wt + ((size_t)(conv * 2 + 0) * NC + nq * 96) * KTOT;
    const bf16* w1 = g_wt + ((size_t)(conv * 2 + 1) * NC + nq * 96) * KTOT;

    float acc[2][6][4];
#pragma unroll
    for (int i = 0; i < 2; i++)
#pragma unroll
        for (int j = 0; j < 6; j++)
#pragma unroll
            for (int k = 0; k < 4; k++) acc[i][j][k] = 0.0f;

    gemm_run<128, 2>(&As[0][0], &Bs[0][0], a0, a1, w0, w1, tx, acc);

    const float* bias = conv ? bg : br;
    const int wid = tx >> 5, lane = tx & 31;
    const int mw = wid >> 1, nw = wid & 1;
    const int gr = lane >> 2, qc = (lane & 3) * 2;
#pragma unroll
    for (int im = 0; im < 2; im++) {
#pragma unroll
        for (int jn = 0; jn < 6; jn++) {
            int ch = nq * 96 + nw * 48 + jn * 8 + qc;
            float bv0 = bias[ch], bv1 = bias[ch + 1];
#pragma unroll
            for (int hf = 0; hf < 2; hf++) {
                int row = mw * 32 + im * 16 + gr + hf * 8;
                float s0 = sigm(acc[im][jn][hf * 2 + 0] + bv0);
                float s1 = sigm(acc[im][jn][hf * 2 + 1] + bv1);
                if (conv == 0) {
                    size_t idx = ((size_t)b * PADL + row + 1) * NC + ch;
                    bf162 h2 = *(const bf162*)(cur0 + idx);
                    bf162 l2 = *(const bf162*)(cur1 + idx);
                    float m0 = __bfloat162float(h2.x) + __bfloat162float(l2.x);
                    float m1 = __bfloat162float(h2.y) + __bfloat162float(l2.y);
                    bf162 hp, lp;
                    split2(s0 * m0, s1 * m1, hp, lp);
                    *(bf162*)(g_t0 + idx) = hp;
                    *(bf162*)(g_t1 + idx) = lp;
                } else {
                    float2 g2;
                    g2.x = s0; g2.y = s1;
                    *(float2*)(g_gate + ((size_t)b * NL + row) * NC + ch) = g2;
                }
            }
        }
    }
}

__global__ void __launch_bounds__(256, 1)
cand_kernel(const bf16* __restrict__ cur0, const bf16* __restrict__ cur1,
            bf16* __restrict__ nxt0, bf16* __restrict__ nxt1,
            const float* __restrict__ bc, float* __restrict__ outp, int last) {
    __shared__ bf16 As[2][64 * 32];
    __shared__ bf16 Bs[2][96 * 32];
    const int tx = threadIdx.x, bx = blockIdx.x;
    const int b = bx >> 2, mh = (bx >> 1) & 1, nq = bx & 1;
    const int r0 = mh * 64;
    const bf16* a0 = g_t0 + ((size_t)b * PADL + r0) * NC;
    const bf16* a1 = g_t1 + ((size_t)b * PADL + r0) * NC;
    const bf16* w0 = g_wt + ((size_t)(2 * 2 + 0) * NC + nq * 96) * KTOT;
    const bf16* w1 = g_wt + ((size_t)(2 * 2 + 1) * NC + nq * 96) * KTOT;

    float acc[1][6][4];
#pragma unroll
    for (int j = 0; j < 6; j++)
#pragma unroll
        for (int k = 0; k < 4; k++) acc[0][j][k] = 0.0f;

    gemm_run<64, 1>(&As[0][0], &Bs[0][0], a0, a1, w0, w1, tx, acc);

    const int wid = tx >> 5, lane = tx & 31;
    const int mw = wid >> 1, nw = wid & 1;
    const int gr = lane >> 2, qc = (lane & 3) * 2;
#pragma unroll
    for (int jn = 0; jn < 6; jn++) {
        int ch = nq * 96 + nw * 48 + jn * 8 + qc;
        float bv0 = bc[ch], bv1 = bc[ch + 1];
#pragma unroll
        for (int hf = 0; hf < 2; hf++) {
            int row = r0 + mw * 16 + gr + hf * 8;
            float c0 = tanhf(acc[0][jn][hf * 2 + 0] + bv0);
            float c1 = tanhf(acc[0][jn][hf * 2 + 1] + bv1);
            float2 g2 = *(const float2*)(g_gate + ((size_t)b * NL + row) * NC + ch);
            size_t sidx = ((size_t)b * PADL + row) * NC + ch;   // mem[row-1]
            bf162 sh2 = *(const bf162*)(cur0 + sidx);
            bf162 sl2 = *(const bf162*)(cur1 + sidx);
            float sh0 = __bfloat162float(sh2.x) + __bfloat162float(sl2.x);
            float sh1 = __bfloat162float(sh2.y) + __bfloat162float(sl2.y);
            float o0 = g2.x * sh0 + (1.0f - g2.x) * c0;
            float o1 = g2.y * sh1 + (1.0f - g2.y) * c1;
            size_t didx = ((size_t)b * PADL + row + 1) * NC + ch;
            bf162 hp, lp;
            split2(o0, o1, hp, lp);
            *(bf162*)(nxt0 + didx) = hp;
            *(bf162*)(nxt1 + didx) = lp;
            if (last) {
                float2 o;
                o.x = o0; o.y = o1;
                *(float2*)(outp + ((size_t)b * NL + row) * NC + ch) = o;
            }
        }
    }
}

// ---------------- prep kernels ----------------
__global__ void zero_kernel() {
    int idx = blockIdx.x * 256 + threadIdx.x;
    const int n4 = NB * PADL * NC / 8;
    if (idx < n4) {
        uint4 z = make_uint4(0, 0, 0, 0);
        ((uint4*)g_ma0)[idx] = z;
        ((uint4*)g_ma1)[idx] = z;
        ((uint4*)g_mb0)[idx] = z;
        ((uint4*)g_mb1)[idx] = z;
        ((uint4*)g_t0)[idx] = z;
        ((uint4*)g_t1)[idx] = z;
    }
}

__global__ void aprep_kernel(const float* __restrict__ x) {
    int idx = blockIdx.x * 256 + threadIdx.x;
    if (idx >= NB * NL * NC) return;
    int ch = idx % NC;
    int l = (idx / NC) % NL;
    int b = idx / (NC * NL);
    float v = x[idx];
    bf16 h = __float2bfloat16(v);
    bf16 lo = __float2bfloat16(v - __bfloat162float(h));
    size_t d = ((size_t)b * PADL + l + 1) * NC + ch;
    g_ma0[d] = h;
    g_ma1[d] = lo;
}

__global__ void wprep_kernel(const float* __restrict__ wr,
                             const float* __restrict__ wg,
                             const float* __restrict__ wc) {
    int idx = blockIdx.x * 256 + threadIdx.x;
    if (idx >= 3 * 3 * NC * NC) return;
    int co = idx % NC;
    int t = idx / NC;
    int ci = t % NC; t /= NC;
    int k = t % 3, c = t / 3;
    const float* w = (c == 0) ? wr : (c == 1) ? wg : wc;
    float v = w[((size_t)k * NC + ci) * NC + co];
    bf16 h = __float2bfloat16(v);
    bf16 lo = __float2bfloat16(v - __bfloat162float(h));
    size_t base = (size_t)k * NC + ci;
    g_wt[((size_t)(c * 2 + 0) * NC + co) * KTOT + base] = h;
    g_wt[((size_t)(c * 2 + 1) * NC + co) * KTOT + base] = lo;
}

extern "C" void kernel_launch(void* const* d_in, const int* in_sizes, int n_in,
                              void* d_out, int out_size) {
    const float* x  = (const float*)d_in[0];
    const float* wr = (const float*)d_in[1];
    const float* br = (const float*)d_in[2];
    const float* wg = (const float*)d_in[3];
    const float* bg = (const float*)d_in[4];
    const float* wc = (const float*)d_in[5];
    const float* bc = (const float*)d_in[6];
    float* out = (float*)d_out;

    bf16 *ma0, *ma1, *mb0, *mb1;
    cudaGetSymbolAddress((void**)&ma0, g_ma0);
    cudaGetSymbolAddress((void**)&ma1, g_ma1);
    cudaGetSymbolAddress((void**)&mb0, g_mb0);
    cudaGetSymbolAddress((void**)&mb1, g_mb1);

    zero_kernel<<<(NB * PADL * NC / 8 + 255) / 256, 256>>>();
    wprep_kernel<<<(3 * 3 * NC * NC + 255) / 256, 256>>>(wr, wg, wc);
    aprep_kernel<<<(NB * NL * NC + 255) / 256, 256>>>(x);

    for (int s = 0; s < NL; s++) {
        bf16* c0 = (s & 1) ? mb0 : ma0;
        bf16* c1 = (s & 1) ? mb1 : ma1;
        bf16* n0 = (s & 1) ? ma0 : mb0;
        bf16* n1 = (s & 1) ? ma1 : mb1;
        rg_kernel<<<128, 256>>>(c0, c1, br, bg);
        cand_kernel<<<128, 256>>>(c0, c1, n0, n1, bc, out, s == NL - 1 ? 1 : 0);
    }
}

// round 7
// speedup vs baseline: 1.9382x; 1.3430x over previous
#include <cuda_runtime.h>
#include <cuda_bf16.h>
#include <cstdint>

// DNGPU recurrence, round 7: split-bf16 HMMA GEMMs with a restructured
// pipeline. vs R6: K-chunks 32->64 (27 iters), 3-stage cp.async ring with a
// SINGLE __syncthreads per iteration, and all swizzled smem addresses
// (cp.async dst + ldmatrix frags) precomputed into registers. Same split
// products A0B0+A1B0+A0B1 (fp32-accurate), same fragment semantics as R6.

typedef __nv_bfloat16 bf16;
typedef __nv_bfloat162 bf162;

#define NB 32
#define NL 128
#define NC 192
#define PADL 130
#define KTOT 576
#define KCH 64
#define NCHUNK 27               // 1728 / 64
#define BBYTES 12288            // 96 rows * 128B

__device__ bf16 g_wt[3 * 2 * NC * KTOT];           // [conv][term][co][k*192+ci]
__device__ bf16 g_ma0[NB * PADL * NC], g_ma1[NB * PADL * NC];
__device__ bf16 g_mb0[NB * PADL * NC], g_mb1[NB * PADL * NC];
__device__ bf16 g_t0[NB * PADL * NC], g_t1[NB * PADL * NC];
__device__ float g_gate[NB * NL * NC];

#define CP16(d, s) \
    asm volatile("cp.async.cg.shared.global [%0], [%1], 16;" :: "r"(d), "l"(s))
#define CP_COMMIT() asm volatile("cp.async.commit_group;" ::: "memory")
#define CP_WAIT(n) asm volatile("cp.async.wait_group %0;" :: "n"(n) : "memory")

__device__ __forceinline__ uint32_t smem_u32(const void* p) {
    uint32_t a;
    asm("{ .reg .u64 t; cvta.to.shared.u64 t, %1; cvt.u32.u64 %0, t; }"
        : "=r"(a) : "l"(p));
    return a;
}
__device__ __forceinline__ void ldsm4(uint32_t (&r)[4], uint32_t a) {
    asm volatile("ldmatrix.sync.aligned.m8n8.x4.shared.b16 {%0,%1,%2,%3}, [%4];"
                 : "=r"(r[0]), "=r"(r[1]), "=r"(r[2]), "=r"(r[3]) : "r"(a));
}
__device__ __forceinline__ void mma16816(float (&c)[4], const uint32_t (&a)[4],
                                         uint32_t b0, uint32_t b1) {
    asm volatile(
        "mma.sync.aligned.m16n8k16.row.col.f32.bf16.bf16.f32 "
        "{%0,%1,%2,%3}, {%4,%5,%6,%7}, {%8,%9}, {%0,%1,%2,%3};"
        : "+f"(c[0]), "+f"(c[1]), "+f"(c[2]), "+f"(c[3])
        : "r"(a[0]), "r"(a[1]), "r"(a[2]), "r"(a[3]), "r"(b0), "r"(b1));
}
__device__ __forceinline__ void split2(float v0, float v1, bf162& hp, bf162& lp) {
    bf16 h0 = __float2bfloat16(v0);
    bf16 h1 = __float2bfloat16(v1);
    hp.x = h0; hp.y = h1;
    lp.x = __float2bfloat16(v0 - __bfloat162float(h0));
    lp.y = __float2bfloat16(v1 - __bfloat162float(h1));
}

// Full K=1728 (3 products x 576) GEMM. Stage layout: [A: M*128B][B: 12288B],
// 128B rows, 16B units, unit swizzle u ^= (row & 7).
template <int M, int MI>
__device__ __forceinline__ void gemm_run(char* ring,
                                         const bf16* __restrict__ a0,
                                         const bf16* __restrict__ a1,
                                         const bf16* __restrict__ b0,
                                         const bf16* __restrict__ b1,
                                         int tx, float (&acc)[MI][6][4]) {
    const uint32_t sbase = smem_u32(ring);
    constexpr int AB = M * 128;
    constexpr int STB = AB + BBYTES;
    constexpr int AJ = M / 32;          // A transfers per thread
    const int wid = tx >> 5, lane = tx & 31;
    const int mw = wid >> 1, nw = wid & 1;

    // ---- precomputed cp.async offsets
    uint32_t dA[AJ]; int sAo[AJ];
#pragma unroll
    for (int j = 0; j < AJ; j++) {
        int idx = tx + j * 256, r = idx >> 3, u = idx & 7;
        dA[j] = r * 128 + (((u ^ (r & 7))) << 4);
        sAo[j] = r * NC + u * 8;
    }
    uint32_t dB[3]; int sBo[3];
#pragma unroll
    for (int j = 0; j < 3; j++) {
        int idx = tx + j * 256, r = idx >> 3, u = idx & 7;
        dB[j] = AB + r * 128 + (((u ^ (r & 7))) << 4);
        sBo[j] = r * KTOT + u * 8;
    }

    // ---- precomputed ldmatrix fragment offsets
    uint32_t offA[MI][4], offB[3][4];
#pragma unroll
    for (int im = 0; im < MI; im++) {
        int row = mw * (16 * MI) + im * 16 + ((lane >> 3) & 1) * 8 + (lane & 7);
#pragma unroll
        for (int h = 0; h < 4; h++)
            offA[im][h] = row * 128 + (((2 * h + (lane >> 4)) ^ (row & 7)) << 4);
    }
#pragma unroll
    for (int j2 = 0; j2 < 3; j2++) {
        int nrow = nw * 48 + j2 * 16 + ((lane >> 4) << 3) + (lane & 7);
#pragma unroll
        for (int h = 0; h < 4; h++)
            offB[j2][h] = AB + nrow * 128 +
                          (((2 * h + ((lane >> 3) & 1)) ^ (nrow & 7)) << 4);
    }

    // ---- chunk issue: q -> product p, tap, ci0
    auto issue = [&](int q) {
        int p = q / 9, kc = q % 9;
        const bf16* ap = ((p == 1) ? a1 : a0) + (kc / 3) * NC + (kc % 3) * KCH;
        const bf16* bp = ((p == 2) ? b1 : b0) + kc * KCH;
        uint32_t st = sbase + (uint32_t)(q % 3) * STB;
#pragma unroll
        for (int j = 0; j < AJ; j++) CP16(st + dA[j], ap + sAo[j]);
#pragma unroll
        for (int j = 0; j < 3; j++) CP16(st + dB[j], bp + sBo[j]);
        CP_COMMIT();
    };

    issue(0);
    issue(1);

#pragma unroll 1
    for (int q = 0; q < NCHUNK; q++) {
        if (q == NCHUNK - 1) { CP_WAIT(0); } else { CP_WAIT(1); }
        __syncthreads();
        if (q + 2 < NCHUNK) issue(q + 2);
        const uint32_t st = sbase + (uint32_t)(q % 3) * STB;
#pragma unroll
        for (int h = 0; h < 4; h++) {
            uint32_t af[MI][4];
#pragma unroll
            for (int im = 0; im < MI; im++) ldsm4(af[im], st + offA[im][h]);
            uint32_t bfm[3][4];
#pragma unroll
            for (int j2 = 0; j2 < 3; j2++) ldsm4(bfm[j2], st + offB[j2][h]);
#pragma unroll
            for (int im = 0; im < MI; im++)
#pragma unroll
                for (int jn = 0; jn < 6; jn++) {
                    int s = (jn & 1) * 2;
                    mma16816(acc[im][jn], af[im], bfm[jn >> 1][s], bfm[jn >> 1][s + 1]);
                }
        }
    }
}

__device__ __forceinline__ float sigm(float x) { return 1.0f / (1.0f + expf(-x)); }

// ---------------- per-step kernels ----------------
__global__ void __launch_bounds__(256, 1)
rg_kernel(const bf16* __restrict__ cur0, const bf16* __restrict__ cur1,
          const float* __restrict__ br, const float* __restrict__ bg) {
    extern __shared__ char ring[];
    const int tx = threadIdx.x, bx = blockIdx.x;
    const int b = bx >> 2, conv = (bx >> 1) & 1, nq = bx & 1;
    const bf16* a0 = cur0 + (size_t)b * PADL * NC;
    const bf16* a1 = cur1 + (size_t)b * PADL * NC;
    const bf16* w0 = g_wt + ((size_t)(conv * 2 + 0) * NC + nq * 96) * KTOT;
    const bf16* w1 = g_wt + ((size_t)(conv * 2 + 1) * NC + nq * 96) * KTOT;

    float acc[2][6][4];
#pragma unroll
    for (int i = 0; i < 2; i++)
#pragma unroll
        for (int j = 0; j < 6; j++)
#pragma unroll
            for (int k = 0; k < 4; k++) acc[i][j][k] = 0.0f;

    gemm_run<128, 2>(ring, a0, a1, w0, w1, tx, acc);

    const float* bias = conv ? bg : br;
    const int wid = tx >> 5, lane = tx & 31;
    const int mw = wid >> 1, nw = wid & 1;
    const int gr = lane >> 2, qc = (lane & 3) * 2;
#pragma unroll
    for (int im = 0; im < 2; im++) {
#pragma unroll
        for (int jn = 0; jn < 6; jn++) {
            int ch = nq * 96 + nw * 48 + jn * 8 + qc;
            float bv0 = bias[ch], bv1 = bias[ch + 1];
#pragma unroll
            for (int hf = 0; hf < 2; hf++) {
                int row = mw * 32 + im * 16 + gr + hf * 8;
                float s0 = sigm(acc[im][jn][hf * 2 + 0] + bv0);
                float s1 = sigm(acc[im][jn][hf * 2 + 1] + bv1);
                if (conv == 0) {
                    size_t idx = ((size_t)b * PADL + row + 1) * NC + ch;
                    bf162 h2 = *(const bf162*)(cur0 + idx);
                    bf162 l2 = *(const bf162*)(cur1 + idx);
                    float m0 = __bfloat162float(h2.x) + __bfloat162float(l2.x);
                    float m1 = __bfloat162float(h2.y) + __bfloat162float(l2.y);
                    bf162 hp, lp;
                    split2(s0 * m0, s1 * m1, hp, lp);
                    *(bf162*)(g_t0 + idx) = hp;
                    *(bf162*)(g_t1 + idx) = lp;
                } else {
                    float2 g2;
                    g2.x = s0; g2.y = s1;
                    *(float2*)(g_gate + ((size_t)b * NL + row) * NC + ch) = g2;
                }
            }
        }
    }
}

__global__ void __launch_bounds__(256, 1)
cand_kernel(const bf16* __restrict__ cur0, const bf16* __restrict__ cur1,
            bf16* __restrict__ nxt0, bf16* __restrict__ nxt1,
            const float* __restrict__ bc, float* __restrict__ outp, int last) {
    extern __shared__ char ring[];
    const int tx = threadIdx.x, bx = blockIdx.x;
    const int b = bx >> 2, mh = (bx >> 1) & 1, nq = bx & 1;
    const int r0 = mh * 64;
    const bf16* a0 = g_t0 + ((size_t)b * PADL + r0) * NC;
    const bf16* a1 = g_t1 + ((size_t)b * PADL + r0) * NC;
    const bf16* w0 = g_wt + ((size_t)(2 * 2 + 0) * NC + nq * 96) * KTOT;
    const bf16* w1 = g_wt + ((size_t)(2 * 2 + 1) * NC + nq * 96) * KTOT;

    float acc[1][6][4];
#pragma unroll
    for (int j = 0; j < 6; j++)
#pragma unroll
        for (int k = 0; k < 4; k++) acc[0][j][k] = 0.0f;

    gemm_run<64, 1>(ring, a0, a1, w0, w1, tx, acc);

    const int wid = tx >> 5, lane = tx & 31;
    const int mw = wid >> 1, nw = wid & 1;
    const int gr = lane >> 2, qc = (lane & 3) * 2;
#pragma unroll
    for (int jn = 0; jn < 6; jn++) {
        int ch = nq * 96 + nw * 48 + jn * 8 + qc;
        float bv0 = bc[ch], bv1 = bc[ch + 1];
#pragma unroll
        for (int hf = 0; hf < 2; hf++) {
            int row = r0 + mw * 16 + gr + hf * 8;
            float c0 = tanhf(acc[0][jn][hf * 2 + 0] + bv0);
            float c1 = tanhf(acc[0][jn][hf * 2 + 1] + bv1);
            float2 g2 = *(const float2*)(g_gate + ((size_t)b * NL + row) * NC + ch);
            size_t sidx = ((size_t)b * PADL + row) * NC + ch;   // mem[row-1]
            bf162 sh2 = *(const bf162*)(cur0 + sidx);
            bf162 sl2 = *(const bf162*)(cur1 + sidx);
            float sh0 = __bfloat162float(sh2.x) + __bfloat162float(sl2.x);
            float sh1 = __bfloat162float(sh2.y) + __bfloat162float(sl2.y);
            float o0 = g2.x * sh0 + (1.0f - g2.x) * c0;
            float o1 = g2.y * sh1 + (1.0f - g2.y) * c1;
            size_t didx = ((size_t)b * PADL + row + 1) * NC + ch;
            bf162 hp, lp;
            split2(o0, o1, hp, lp);
            *(bf162*)(nxt0 + didx) = hp;
            *(bf162*)(nxt1 + didx) = lp;
            if (last) {
                float2 o;
                o.x = o0; o.y = o1;
                *(float2*)(outp + ((size_t)b * NL + row) * NC + ch) = o;
            }
        }
    }
}

// ---------------- prep kernels ----------------
__global__ void zero_kernel() {
    int idx = blockIdx.x * 256 + threadIdx.x;
    const int n4 = NB * PADL * NC / 8;
    if (idx < n4) {
        uint4 z = make_uint4(0, 0, 0, 0);
        ((uint4*)g_ma0)[idx] = z;
        ((uint4*)g_ma1)[idx] = z;
        ((uint4*)g_mb0)[idx] = z;
        ((uint4*)g_mb1)[idx] = z;
        ((uint4*)g_t0)[idx] = z;
        ((uint4*)g_t1)[idx] = z;
    }
}

__global__ void aprep_kernel(const float* __restrict__ x) {
    int idx = blockIdx.x * 256 + threadIdx.x;
    if (idx >= NB * NL * NC) return;
    int ch = idx % NC;
    int l = (idx / NC) % NL;
    int b = idx / (NC * NL);
    float v = x[idx];
    bf16 h = __float2bfloat16(v);
    bf16 lo = __float2bfloat16(v - __bfloat162float(h));
    size_t d = ((size_t)b * PADL + l + 1) * NC + ch;
    g_ma0[d] = h;
    g_ma1[d] = lo;
}

__global__ void wprep_kernel(const float* __restrict__ wr,
                             const float* __restrict__ wg,
                             const float* __restrict__ wc) {
    int idx = blockIdx.x * 256 + threadIdx.x;
    if (idx >= 3 * 3 * NC * NC) return;
    int co = idx % NC;
    int t = idx / NC;
    int ci = t % NC; t /= NC;
    int k = t % 3, c = t / 3;
    const float* w = (c == 0) ? wr : (c == 1) ? wg : wc;
    float v = w[((size_t)k * NC + ci) * NC + co];
    bf16 h = __float2bfloat16(v);
    bf16 lo = __float2bfloat16(v - __bfloat162float(h));
    size_t base = (size_t)k * NC + ci;
    g_wt[((size_t)(c * 2 + 0) * NC + co) * KTOT + base] = h;
    g_wt[((size_t)(c * 2 + 1) * NC + co) * KTOT + base] = lo;
}

extern "C" void kernel_launch(void* const* d_in, const int* in_sizes, int n_in,
                              void* d_out, int out_size) {
    const float* x  = (const float*)d_in[0];
    const float* wr = (const float*)d_in[1];
    const float* br = (const float*)d_in[2];
    const float* wg = (const float*)d_in[3];
    const float* bg = (const float*)d_in[4];
    const float* wc = (const float*)d_in[5];
    const float* bc = (const float*)d_in[6];
    float* out = (float*)d_out;

    bf16 *ma0, *ma1, *mb0, *mb1;
    cudaGetSymbolAddress((void**)&ma0, g_ma0);
    cudaGetSymbolAddress((void**)&ma1, g_ma1);
    cudaGetSymbolAddress((void**)&mb0, g_mb0);
    cudaGetSymbolAddress((void**)&mb1, g_mb1);

    const int RG_SMEM = 3 * (128 * 128 + BBYTES);    // 86016
    const int CD_SMEM = 3 * (64 * 128 + BBYTES);     // 61440
    cudaFuncSetAttribute(rg_kernel, cudaFuncAttributeMaxDynamicSharedMemorySize,
                         RG_SMEM);
    cudaFuncSetAttribute(cand_kernel, cudaFuncAttributeMaxDynamicSharedMemorySize,
                         CD_SMEM);

    zero_kernel<<<(NB * PADL * NC / 8 + 255) / 256, 256>>>();
    wprep_kernel<<<(3 * 3 * NC * NC + 255) / 256, 256>>>(wr, wg, wc);
    aprep_kernel<<<(NB * NL * NC + 255) / 256, 256>>>(x);

    for (int s = 0; s < NL; s++) {
        bf16* c0 = (s & 1) ? mb0 : ma0;
        bf16* c1 = (s & 1) ? mb1 : ma1;
        bf16* n0 = (s & 1) ? ma0 : mb0;
        bf16* n1 = (s & 1) ? ma1 : mb1;
        rg_kernel<<<128, 256, RG_SMEM>>>(c0, c1, br, bg);
        cand_kernel<<<128, 256, CD_SMEM>>>(c0, c1, n0, n1, bc, out,
                                           s == NL - 1 ? 1 : 0);
    }
}

// round 8
// speedup vs baseline: 2.1373x; 1.1027x over previous
#include <cuda_runtime.h>
#include <cuda_bf16.h>
#include <cstdint>

// DNGPU recurrence, round 8: occupancy-2 split-bf16 HMMA GEMMs.
// vs R7: N-quarter tiles (48 cols/CTA) double the grid to 256 CTAs and
// shrink smem so TWO CTAs co-reside per SM (__launch_bounds__(256,2)) --
// when one CTA sits at its per-chunk barrier the other keeps the tensor
// pipe busy. Total A/B global traffic per launch is unchanged vs R7.
// Same split products A0B0+A1B0+A0B1 (fp32-accurate), 3-stage cp.async
// ring, one __syncthreads per chunk, precomputed swizzled addresses.
// B fragments use ldmatrix.x2 (one n8 tile, two K-halves) for the
// 24-col-per-warp slice.

typedef __nv_bfloat16 bf16;
typedef __nv_bfloat162 bf162;

#define NB 32
#define NL 128
#define NC 192
#define PADL 130
#define KTOT 576
#define KCH 64
#define NCHUNK 27               // 1728 / 64
#define BROWS 48
#define BBYTES (BROWS * 128)    // 6144

__device__ bf16 g_wt[3 * 2 * NC * KTOT];           // [conv][term][co][k*192+ci]
__device__ bf16 g_ma0[NB * PADL * NC], g_ma1[NB * PADL * NC];
__device__ bf16 g_mb0[NB * PADL * NC], g_mb1[NB * PADL * NC];
__device__ bf16 g_t0[NB * PADL * NC], g_t1[NB * PADL * NC];
__device__ float g_gate[NB * NL * NC];

#define CP16(d, s) \
    asm volatile("cp.async.cg.shared.global [%0], [%1], 16;" :: "r"(d), "l"(s))
#define CP_COMMIT() asm volatile("cp.async.commit_group;" ::: "memory")
#define CP_WAIT(n) asm volatile("cp.async.wait_group %0;" :: "n"(n) : "memory")

__device__ __forceinline__ uint32_t smem_u32(const void* p) {
    uint32_t a;
    asm("{ .reg .u64 t; cvta.to.shared.u64 t, %1; cvt.u32.u64 %0, t; }"
        : "=r"(a) : "l"(p));
    return a;
}
__device__ __forceinline__ void ldsm4(uint32_t (&r)[4], uint32_t a) {
    asm volatile("ldmatrix.sync.aligned.m8n8.x4.shared.b16 {%0,%1,%2,%3}, [%4];"
                 : "=r"(r[0]), "=r"(r[1]), "=r"(r[2]), "=r"(r[3]) : "r"(a));
}
__device__ __forceinline__ void ldsm2(uint32_t (&r)[2], uint32_t a) {
    asm volatile("ldmatrix.sync.aligned.m8n8.x2.shared.b16 {%0,%1}, [%2];"
                 : "=r"(r[0]), "=r"(r[1]) : "r"(a));
}
__device__ __forceinline__ void mma16816(float (&c)[4], const uint32_t (&a)[4],
                                         uint32_t b0, uint32_t b1) {
    asm volatile(
        "mma.sync.aligned.m16n8k16.row.col.f32.bf16.bf16.f32 "
        "{%0,%1,%2,%3}, {%4,%5,%6,%7}, {%8,%9}, {%0,%1,%2,%3};"
        : "+f"(c[0]), "+f"(c[1]), "+f"(c[2]), "+f"(c[3])
        : "r"(a[0]), "r"(a[1]), "r"(a[2]), "r"(a[3]), "r"(b0), "r"(b1));
}
__device__ __forceinline__ void split2(float v0, float v1, bf162& hp, bf162& lp) {
    bf16 h0 = __float2bfloat16(v0);
    bf16 h1 = __float2bfloat16(v1);
    hp.x = h0; hp.y = h1;
    lp.x = __float2bfloat16(v0 - __bfloat162float(h0));
    lp.y = __float2bfloat16(v1 - __bfloat162float(h1));
}

// Full K=1728 (3 products x 576) GEMM. Stage layout: [A: M*128B][B: 6144B],
// 128B rows, 16B units, unit swizzle u ^= (row & 7). Warps: 4 mw x 2 nw(24).
template <int M, int MI>
__device__ __forceinline__ void gemm_run(char* ring,
                                         const bf16* __restrict__ a0,
                                         const bf16* __restrict__ a1,
                                         const bf16* __restrict__ b0,
                                         const bf16* __restrict__ b1,
                                         int tx, float (&acc)[MI][3][4]) {
    const uint32_t sbase = smem_u32(ring);
    constexpr int AB = M * 128;
    constexpr int STB = AB + BBYTES;
    constexpr int AJ = M / 32;          // A transfers per thread
    const int wid = tx >> 5, lane = tx & 31;
    const int mw = wid >> 1, nw = wid & 1;

    // ---- precomputed cp.async offsets
    uint32_t dA[AJ]; int sAo[AJ];
#pragma unroll
    for (int j = 0; j < AJ; j++) {
        int idx = tx + j * 256, r = idx >> 3, u = idx & 7;
        dA[j] = r * 128 + (((u ^ (r & 7))) << 4);
        sAo[j] = r * NC + u * 8;
    }
    // B: 48 rows x 8 units = 384 transfers; threads 0..127 do 2, rest 1.
    uint32_t dB[2]; int sBo[2]; bool vB1;
    {
        int r = tx >> 3, u = tx & 7;
        dB[0] = AB + r * 128 + (((u ^ (r & 7))) << 4);
        sBo[0] = r * KTOT + u * 8;
        int idx = tx + 256;
        vB1 = idx < 384;
        int r1 = idx >> 3, u1 = idx & 7;
        dB[1] = AB + r1 * 128 + (((u1 ^ (r1 & 7))) << 4);
        sBo[1] = r1 * KTOT + u1 * 8;
    }

    // ---- precomputed ldmatrix fragment offsets
    uint32_t offA[MI][4], offB[3][4];
#pragma unroll
    for (int im = 0; im < MI; im++) {
        int row = mw * (16 * MI) + im * 16 + ((lane >> 3) & 1) * 8 + (lane & 7);
#pragma unroll
        for (int h = 0; h < 4; h++)
            offA[im][h] = row * 128 + (((2 * h + (lane >> 4)) ^ (row & 7)) << 4);
    }
#pragma unroll
    for (int j2 = 0; j2 < 3; j2++) {
        int l16 = lane & 15;
        int nrow = nw * 24 + j2 * 8 + (l16 & 7);
#pragma unroll
        for (int h = 0; h < 4; h++)
            offB[j2][h] = AB + nrow * 128 +
                          (((2 * h + ((l16 >> 3) & 1)) ^ (nrow & 7)) << 4);
    }

    // ---- chunk issue: q -> product p, tap, ci0
    auto issue = [&](int q) {
        int p = q / 9, kc = q % 9;
        const bf16* ap = ((p == 1) ? a1 : a0) + (kc / 3) * NC + (kc % 3) * KCH;
        const bf16* bp = ((p == 2) ? b1 : b0) + kc * KCH;
        uint32_t st = sbase + (uint32_t)(q % 3) * STB;
#pragma unroll
        for (int j = 0; j < AJ; j++) CP16(st + dA[j], ap + sAo[j]);
        CP16(st + dB[0], bp + sBo[0]);
        if (vB1) CP16(st + dB[1], bp + sBo[1]);
        CP_COMMIT();
    };

    issue(0);
    issue(1);

#pragma unroll 1
    for (int q = 0; q < NCHUNK; q++) {
        if (q == NCHUNK - 1) { CP_WAIT(0); } else { CP_WAIT(1); }
        __syncthreads();
        if (q + 2 < NCHUNK) issue(q + 2);
        const uint32_t st = sbase + (uint32_t)(q % 3) * STB;
#pragma unroll
        for (int h = 0; h < 4; h++) {
            uint32_t af[MI][4];
#pragma unroll
            for (int im = 0; im < MI; im++) ldsm4(af[im], st + offA[im][h]);
            uint32_t bf2[3][2];
#pragma unroll
            for (int j2 = 0; j2 < 3; j2++) ldsm2(bf2[j2], st + offB[j2][h]);
#pragma unroll
            for (int im = 0; im < MI; im++)
#pragma unroll
                for (int jn = 0; jn < 3; jn++)
                    mma16816(acc[im][jn], af[im], bf2[jn][0], bf2[jn][1]);
        }
    }
}

__device__ __forceinline__ float sigm(float x) { return 1.0f / (1.0f + expf(-x)); }

// ---------------- per-step kernels ----------------
__global__ void __launch_bounds__(256, 2)
rg_kernel(const bf16* __restrict__ cur0, const bf16* __restrict__ cur1,
          const float* __restrict__ br, const float* __restrict__ bg) {
    extern __shared__ char ring[];
    const int tx = threadIdx.x, bx = blockIdx.x;
    const int b = bx >> 3, conv = (bx >> 2) & 1, nq = bx & 3;
    const bf16* a0 = cur0 + (size_t)b * PADL * NC;
    const bf16* a1 = cur1 + (size_t)b * PADL * NC;
    const bf16* w0 = g_wt + ((size_t)(conv * 2 + 0) * NC + nq * BROWS) * KTOT;
    const bf16* w1 = g_wt + ((size_t)(conv * 2 + 1) * NC + nq * BROWS) * KTOT;

    float acc[2][3][4];
#pragma unroll
    for (int i = 0; i < 2; i++)
#pragma unroll
        for (int j = 0; j < 3; j++)
#pragma unroll
            for (int k = 0; k < 4; k++) acc[i][j][k] = 0.0f;

    gemm_run<128, 2>(ring, a0, a1, w0, w1, tx, acc);

    const float* bias = conv ? bg : br;
    const int wid = tx >> 5, lane = tx & 31;
    const int mw = wid >> 1, nw = wid & 1;
    const int gr = lane >> 2, qc = (lane & 3) * 2;
#pragma unroll
    for (int im = 0; im < 2; im++) {
#pragma unroll
        for (int jn = 0; jn < 3; jn++) {
            int ch = nq * BROWS + nw * 24 + jn * 8 + qc;
            float bv0 = bias[ch], bv1 = bias[ch + 1];
#pragma unroll
            for (int hf = 0; hf < 2; hf++) {
                int row = mw * 32 + im * 16 + gr + hf * 8;
                float s0 = sigm(acc[im][jn][hf * 2 + 0] + bv0);
                float s1 = sigm(acc[im][jn][hf * 2 + 1] + bv1);
                if (conv == 0) {
                    size_t idx = ((size_t)b * PADL + row + 1) * NC + ch;
                    bf162 h2 = *(const bf162*)(cur0 + idx);
                    bf162 l2 = *(const bf162*)(cur1 + idx);
                    float m0 = __bfloat162float(h2.x) + __bfloat162float(l2.x);
                    float m1 = __bfloat162float(h2.y) + __bfloat162float(l2.y);
                    bf162 hp, lp;
                    split2(s0 * m0, s1 * m1, hp, lp);
                    *(bf162*)(g_t0 + idx) = hp;
                    *(bf162*)(g_t1 + idx) = lp;
                } else {
                    float2 g2;
                    g2.x = s0; g2.y = s1;
                    *(float2*)(g_gate + ((size_t)b * NL + row) * NC + ch) = g2;
                }
            }
        }
    }
}

__global__ void __launch_bounds__(256, 2)
cand_kernel(const bf16* __restrict__ cur0, const bf16* __restrict__ cur1,
            bf16* __restrict__ nxt0, bf16* __restrict__ nxt1,
            const float* __restrict__ bc, float* __restrict__ outp, int last) {
    extern __shared__ char ring[];
    const int tx = threadIdx.x, bx = blockIdx.x;
    const int b = bx >> 3, mh = (bx >> 2) & 1, nq = bx & 3;
    const int r0 = mh * 64;
    const bf16* a0 = g_t0 + ((size_t)b * PADL + r0) * NC;
    const bf16* a1 = g_t1 + ((size_t)b * PADL + r0) * NC;
    const bf16* w0 = g_wt + ((size_t)(2 * 2 + 0) * NC + nq * BROWS) * KTOT;
    const bf16* w1 = g_wt + ((size_t)(2 * 2 + 1) * NC + nq * BROWS) * KTOT;

    float acc[1][3][4];
#pragma unroll
    for (int j = 0; j < 3; j++)
#pragma unroll
        for (int k = 0; k < 4; k++) acc[0][j][k] = 0.0f;

    gemm_run<64, 1>(ring, a0, a1, w0, w1, tx, acc);

    const int wid = tx >> 5, lane = tx & 31;
    const int mw = wid >> 1, nw = wid & 1;
    const int gr = lane >> 2, qc = (lane & 3) * 2;
#pragma unroll
    for (int jn = 0; jn < 3; jn++) {
        int ch = nq * BROWS + nw * 24 + jn * 8 + qc;
        float bv0 = bc[ch], bv1 = bc[ch + 1];
#pragma unroll
        for (int hf = 0; hf < 2; hf++) {
            int row = r0 + mw * 16 + gr + hf * 8;
            float c0 = tanhf(acc[0][jn][hf * 2 + 0] + bv0);
            float c1 = tanhf(acc[0][jn][hf * 2 + 1] + bv1);
            float2 g2 = *(const float2*)(g_gate + ((size_t)b * NL + row) * NC + ch);
            size_t sidx = ((size_t)b * PADL + row) * NC + ch;   // mem[row-1]
            bf162 sh2 = *(const bf162*)(cur0 + sidx);
            bf162 sl2 = *(const bf162*)(cur1 + sidx);
            float sh0 = __bfloat162float(sh2.x) + __bfloat162float(sl2.x);
            float sh1 = __bfloat162float(sh2.y) + __bfloat162float(sl2.y);
            float o0 = g2.x * sh0 + (1.0f - g2.x) * c0;
            float o1 = g2.y * sh1 + (1.0f - g2.y) * c1;
            size_t didx = ((size_t)b * PADL + row + 1) * NC + ch;
            bf162 hp, lp;
            split2(o0, o1, hp, lp);
            *(bf162*)(nxt0 + didx) = hp;
            *(bf162*)(nxt1 + didx) = lp;
            if (last) {
                float2 o;
                o.x = o0; o.y = o1;
                *(float2*)(outp + ((size_t)b * NL + row) * NC + ch) = o;
            }
        }
    }
}

// ---------------- prep kernels ----------------
__global__ void zero_kernel() {
    int idx = blockIdx.x * 256 + threadIdx.x;
    const int n4 = NB * PADL * NC / 8;
    if (idx < n4) {
        uint4 z = make_uint4(0, 0, 0, 0);
        ((uint4*)g_ma0)[idx] = z;
        ((uint4*)g_ma1)[idx] = z;
        ((uint4*)g_mb0)[idx] = z;
        ((uint4*)g_mb1)[idx] = z;
        ((uint4*)g_t0)[idx] = z;
        ((uint4*)g_t1)[idx] = z;
    }
}

__global__ void aprep_kernel(const float* __restrict__ x) {
    int idx = blockIdx.x * 256 + threadIdx.x;
    if (idx >= NB * NL * NC) return;
    int ch = idx % NC;
    int l = (idx / NC) % NL;
    int b = idx / (NC * NL);
    float v = x[idx];
    bf16 h = __float2bfloat16(v);
    bf16 lo = __float2bfloat16(v - __bfloat162float(h));
    size_t d = ((size_t)b * PADL + l + 1) * NC + ch;
    g_ma0[d] = h;
    g_ma1[d] = lo;
}

__global__ void wprep_kernel(const float* __restrict__ wr,
                             const float* __restrict__ wg,
                             const float* __restrict__ wc) {
    int idx = blockIdx.x * 256 + threadIdx.x;
    if (idx >= 3 * 3 * NC * NC) return;
    int co = idx % NC;
    int t = idx / NC;
    int ci = t % NC; t /= NC;
    int k = t % 3, c = t / 3;
    const float* w = (c == 0) ? wr : (c == 1) ? wg : wc;
    float v = w[((size_t)k * NC + ci) * NC + co];
    bf16 h = __float2bfloat16(v);
    bf16 lo = __float2bfloat16(v - __bfloat162float(h));
    size_t base = (size_t)k * NC + ci;
    g_wt[((size_t)(c * 2 + 0) * NC + co) * KTOT + base] = h;
    g_wt[((size_t)(c * 2 + 1) * NC + co) * KTOT + base] = lo;
}

extern "C" void kernel_launch(void* const* d_in, const int* in_sizes, int n_in,
                              void* d_out, int out_size) {
    const float* x  = (const float*)d_in[0];
    const float* wr = (const float*)d_in[1];
    const float* br = (const float*)d_in[2];
    const float* wg = (const float*)d_in[3];
    const float* bg = (const float*)d_in[4];
    const float* wc = (const float*)d_in[5];
    const float* bc = (const float*)d_in[6];
    float* out = (float*)d_out;

    bf16 *ma0, *ma1, *mb0, *mb1;
    cudaGetSymbolAddress((void**)&ma0, g_ma0);
    cudaGetSymbolAddress((void**)&ma1, g_ma1);
    cudaGetSymbolAddress((void**)&mb0, g_mb0);
    cudaGetSymbolAddress((void**)&mb1, g_mb1);

    const int RG_SMEM = 3 * (128 * 128 + BBYTES);    // 67584
    const int CD_SMEM = 3 * (64 * 128 + BBYTES);     // 43008
    cudaFuncSetAttribute(rg_kernel, cudaFuncAttributeMaxDynamicSharedMemorySize,
                         RG_SMEM);
    cudaFuncSetAttribute(cand_kernel, cudaFuncAttributeMaxDynamicSharedMemorySize,
                         CD_SMEM);

    zero_kernel<<<(NB * PADL * NC / 8 + 255) / 256, 256>>>();
    wprep_kernel<<<(3 * 3 * NC * NC + 255) / 256, 256>>>(wr, wg, wc);
    aprep_kernel<<<(NB * NL * NC + 255) / 256, 256>>>(x);

    for (int s = 0; s < NL; s++) {
        bf16* c0 = (s & 1) ? mb0 : ma0;
        bf16* c1 = (s & 1) ? mb1 : ma1;
        bf16* n0 = (s & 1) ? ma0 : mb0;
        bf16* n1 = (s & 1) ? ma1 : mb1;
        rg_kernel<<<256, 256, RG_SMEM>>>(c0, c1, br, bg);
        cand_kernel<<<256, 256, CD_SMEM>>>(c0, c1, n0, n1, bc, out,
                                           s == NL - 1 ? 1 : 0);
    }
}

// round 9
// speedup vs baseline: 2.2149x; 1.0363x over previous
#include <cuda_runtime.h>
#include <cuda_bf16.h>
#include <cstdint>

// DNGPU recurrence, round 9: occupancy-2 split-bf16 HMMA GEMMs.
// vs R8: (1) 4-stage cp.async ring with ONE CP_WAIT(0)+__syncthreads per
// chunk PAIR (14 barriers instead of 27) -- at each pair sync the stages of
// chunks q+2,q+3 are provably free, so prefetch issues overlap the pair's
// compute; (2) B fragments packed as 1 ldmatrix.x4 (j2=0,1) + 1 ldmatrix.x2
// (j2=2) per K16-half (was 3 ldmatrix.x2), cutting smem instructions 20%.
// Same split products A0B0+A1B0+A0B1, same per-tile addresses -> identical
// numerics to R8.

typedef __nv_bfloat16 bf16;
typedef __nv_bfloat162 bf162;

#define NB 32
#define NL 128
#define NC 192
#define PADL 130
#define KTOT 576
#define KCH 64
#define NCHUNK 27               // 1728 / 64
#define NPAIR 14
#define BROWS 48
#define BBYTES (BROWS * 128)    // 6144

__device__ bf16 g_wt[3 * 2 * NC * KTOT];           // [conv][term][co][k*192+ci]
__device__ bf16 g_ma0[NB * PADL * NC], g_ma1[NB * PADL * NC];
__device__ bf16 g_mb0[NB * PADL * NC], g_mb1[NB * PADL * NC];
__device__ bf16 g_t0[NB * PADL * NC], g_t1[NB * PADL * NC];
__device__ float g_gate[NB * NL * NC];

#define CP16(d, s) \
    asm volatile("cp.async.cg.shared.global [%0], [%1], 16;" :: "r"(d), "l"(s))
#define CP_COMMIT() asm volatile("cp.async.commit_group;" ::: "memory")
#define CP_WAIT(n) asm volatile("cp.async.wait_group %0;" :: "n"(n) : "memory")

__device__ __forceinline__ uint32_t smem_u32(const void* p) {
    uint32_t a;
    asm("{ .reg .u64 t; cvta.to.shared.u64 t, %1; cvt.u32.u64 %0, t; }"
        : "=r"(a) : "l"(p));
    return a;
}
__device__ __forceinline__ void ldsm4(uint32_t (&r)[4], uint32_t a) {
    asm volatile("ldmatrix.sync.aligned.m8n8.x4.shared.b16 {%0,%1,%2,%3}, [%4];"
                 : "=r"(r[0]), "=r"(r[1]), "=r"(r[2]), "=r"(r[3]) : "r"(a));
}
__device__ __forceinline__ void ldsm2(uint32_t (&r)[2], uint32_t a) {
    asm volatile("ldmatrix.sync.aligned.m8n8.x2.shared.b16 {%0,%1}, [%2];"
                 : "=r"(r[0]), "=r"(r[1]) : "r"(a));
}
__device__ __forceinline__ void mma16816(float (&c)[4], const uint32_t (&a)[4],
                                         uint32_t b0, uint32_t b1) {
    asm volatile(
        "mma.sync.aligned.m16n8k16.row.col.f32.bf16.bf16.f32 "
        "{%0,%1,%2,%3}, {%4,%5,%6,%7}, {%8,%9}, {%0,%1,%2,%3};"
        : "+f"(c[0]), "+f"(c[1]), "+f"(c[2]), "+f"(c[3])
        : "r"(a[0]), "r"(a[1]), "r"(a[2]), "r"(a[3]), "r"(b0), "r"(b1));
}
__device__ __forceinline__ void split2(float v0, float v1, bf162& hp, bf162& lp) {
    bf16 h0 = __float2bfloat16(v0);
    bf16 h1 = __float2bfloat16(v1);
    hp.x = h0; hp.y = h1;
    lp.x = __float2bfloat16(v0 - __bfloat162float(h0));
    lp.y = __float2bfloat16(v1 - __bfloat162float(h1));
}

// Full K=1728 (3 products x 576) GEMM. Stage layout: [A: M*128B][B: 6144B],
// 128B rows, 16B units, unit swizzle u ^= (row & 7). Warps: 4 mw x 2 nw(24).
template <int M, int MI>
__device__ __forceinline__ void gemm_run(char* ring,
                                         const bf16* __restrict__ a0,
                                         const bf16* __restrict__ a1,
                                         const bf16* __restrict__ b0,
                                         const bf16* __restrict__ b1,
                                         int tx, float (&acc)[MI][3][4]) {
    const uint32_t sbase = smem_u32(ring);
    constexpr int AB = M * 128;
    constexpr int STB = AB + BBYTES;    // one chunk stage
    constexpr int AJ = M / 32;          // A transfers per thread
    const int wid = tx >> 5, lane = tx & 31;
    const int mw = wid >> 1, nw = wid & 1;

    // ---- precomputed cp.async offsets
    uint32_t dA[AJ]; int sAo[AJ];
#pragma unroll
    for (int j = 0; j < AJ; j++) {
        int idx = tx + j * 256, r = idx >> 3, u = idx & 7;
        dA[j] = r * 128 + (((u ^ (r & 7))) << 4);
        sAo[j] = r * NC + u * 8;
    }
    // B: 48 rows x 8 units = 384 transfers; threads 0..127 do 2, rest 1.
    uint32_t dB[2]; int sBo[2]; bool vB1;
    {
        int r = tx >> 3, u = tx & 7;
        dB[0] = AB + r * 128 + (((u ^ (r & 7))) << 4);
        sBo[0] = r * KTOT + u * 8;
        int idx = tx + 256;
        vB1 = idx < 384;
        int r1 = idx >> 3, u1 = idx & 7;
        dB[1] = AB + r1 * 128 + (((u1 ^ (r1 & 7))) << 4);
        sBo[1] = r1 * KTOT + u1 * 8;
    }

    // ---- precomputed ldmatrix fragment offsets
    uint32_t offA[MI][4], offB4[4], offB2[4];
#pragma unroll
    for (int im = 0; im < MI; im++) {
        int row = mw * (16 * MI) + im * 16 + ((lane >> 3) & 1) * 8 + (lane & 7);
#pragma unroll
        for (int h = 0; h < 4; h++)
            offA[im][h] = row * 128 + (((2 * h + (lane >> 4)) ^ (row & 7)) << 4);
    }
    {
        // x4: tiles (j2=0,k0),(j2=0,k1),(j2=1,k0),(j2=1,k1) via lane groups
        int grp = lane >> 3;            // 0..3
        int j2s = grp >> 1, khs = grp & 1;
        int nrow = nw * 24 + j2s * 8 + (lane & 7);
#pragma unroll
        for (int h = 0; h < 4; h++)
            offB4[h] = AB + nrow * 128 +
                       (((2 * h + khs) ^ (nrow & 7)) << 4);
        // x2: tile j2=2, two k-halves via lane groups 0,1 (lanes 0..15)
        int nrow2 = nw * 24 + 16 + (lane & 7);
        int kh2 = (lane >> 3) & 1;
#pragma unroll
        for (int h = 0; h < 4; h++)
            offB2[h] = AB + nrow2 * 128 +
                       (((2 * h + kh2) ^ (nrow2 & 7)) << 4);
    }

    // ---- chunk issue: q -> product p, tap, ci0; one commit group per chunk
    auto issue = [&](int q) {
        int p = q / 9, kc = q % 9;
        const bf16* ap = ((p == 1) ? a1 : a0) + (kc / 3) * NC + (kc % 3) * KCH;
        const bf16* bp = ((p == 2) ? b1 : b0) + kc * KCH;
        uint32_t st = sbase + (uint32_t)(q & 3) * STB;
#pragma unroll
        for (int j = 0; j < AJ; j++) CP16(st + dA[j], ap + sAo[j]);
        CP16(st + dB[0], bp + sBo[0]);
        if (vB1) CP16(st + dB[1], bp + sBo[1]);
        CP_COMMIT();
    };

    auto compute = [&](int q) {
        const uint32_t st = sbase + (uint32_t)(q & 3) * STB;
#pragma unroll
        for (int h = 0; h < 4; h++) {
            uint32_t af[MI][4];
#pragma unroll
            for (int im = 0; im < MI; im++) ldsm4(af[im], st + offA[im][h]);
            uint32_t bq[4];
            ldsm4(bq, st + offB4[h]);
            uint32_t b2[2];
            ldsm2(b2, st + offB2[h]);
#pragma unroll
            for (int im = 0; im < MI; im++) {
                mma16816(acc[im][0], af[im], bq[0], bq[1]);
                mma16816(acc[im][1], af[im], bq[2], bq[3]);
                mma16816(acc[im][2], af[im], b2[0], b2[1]);
            }
        }
    };

    issue(0);
    issue(1);

#pragma unroll 1
    for (int P = 0; P < NPAIR; P++) {
        const int q = 2 * P;
        CP_WAIT(0);                 // chunks q and q+1 landed
        __syncthreads();            // visibility + release of stages q+2,q+3
        if (q + 2 < NCHUNK) issue(q + 2);
        if (q + 3 < NCHUNK) issue(q + 3);
        compute(q);
        if (q + 1 < NCHUNK) compute(q + 1);
    }
}

__device__ __forceinline__ float sigm(float x) { return 1.0f / (1.0f + expf(-x)); }

// ---------------- per-step kernels ----------------
__global__ void __launch_bounds__(256, 2)
rg_kernel(const bf16* __restrict__ cur0, const bf16* __restrict__ cur1,
          const float* __restrict__ br, const float* __restrict__ bg) {
    extern __shared__ char ring[];
    const int tx = threadIdx.x, bx = blockIdx.x;
    const int b = bx >> 3, conv = (bx >> 2) & 1, nq = bx & 3;
    const bf16* a0 = cur0 + (size_t)b * PADL * NC;
    const bf16* a1 = cur1 + (size_t)b * PADL * NC;
    const bf16* w0 = g_wt + ((size_t)(conv * 2 + 0) * NC + nq * BROWS) * KTOT;
    const bf16* w1 = g_wt + ((size_t)(conv * 2 + 1) * NC + nq * BROWS) * KTOT;

    float acc[2][3][4];
#pragma unroll
    for (int i = 0; i < 2; i++)
#pragma unroll
        for (int j = 0; j < 3; j++)
#pragma unroll
            for (int k = 0; k < 4; k++) acc[i][j][k] = 0.0f;

    gemm_run<128, 2>(ring, a0, a1, w0, w1, tx, acc);

    const float* bias = conv ? bg : br;
    const int wid = tx >> 5, lane = tx & 31;
    const int mw = wid >> 1, nw = wid & 1;
    const int gr = lane >> 2, qc = (lane & 3) * 2;
#pragma unroll
    for (int im = 0; im < 2; im++) {
#pragma unroll
        for (int jn = 0; jn < 3; jn++) {
            int ch = nq * BROWS + nw * 24 + jn * 8 + qc;
            float bv0 = bias[ch], bv1 = bias[ch + 1];
#pragma unroll
            for (int hf = 0; hf < 2; hf++) {
                int row = mw * 32 + im * 16 + gr + hf * 8;
                float s0 = sigm(acc[im][jn][hf * 2 + 0] + bv0);
                float s1 = sigm(acc[im][jn][hf * 2 + 1] + bv1);
                if (conv == 0) {
                    size_t idx = ((size_t)b * PADL + row + 1) * NC + ch;
                    bf162 h2 = *(const bf162*)(cur0 + idx);
                    bf162 l2 = *(const bf162*)(cur1 + idx);
                    float m0 = __bfloat162float(h2.x) + __bfloat162float(l2.x);
                    float m1 = __bfloat162float(h2.y) + __bfloat162float(l2.y);
                    bf162 hp, lp;
                    split2(s0 * m0, s1 * m1, hp, lp);
                    *(bf162*)(g_t0 + idx) = hp;
                    *(bf162*)(g_t1 + idx) = lp;
                } else {
                    float2 g2;
                    g2.x = s0; g2.y = s1;
                    *(float2*)(g_gate + ((size_t)b * NL + row) * NC + ch) = g2;
                }
            }
        }
    }
}

__global__ void __launch_bounds__(256, 2)
cand_kernel(const bf16* __restrict__ cur0, const bf16* __restrict__ cur1,
            bf16* __restrict__ nxt0, bf16* __restrict__ nxt1,
            const float* __restrict__ bc, float* __restrict__ outp, int last) {
    extern __shared__ char ring[];
    const int tx = threadIdx.x, bx = blockIdx.x;
    const int b = bx >> 3, mh = (bx >> 2) & 1, nq = bx & 3;
    const int r0 = mh * 64;
    const bf16* a0 = g_t0 + ((size_t)b * PADL + r0) * NC;
    const bf16* a1 = g_t1 + ((size_t)b * PADL + r0) * NC;
    const bf16* w0 = g_wt + ((size_t)(2 * 2 + 0) * NC + nq * BROWS) * KTOT;
    const bf16* w1 = g_wt + ((size_t)(2 * 2 + 1) * NC + nq * BROWS) * KTOT;

    float acc[1][3][4];
#pragma unroll
    for (int j = 0; j < 3; j++)
#pragma unroll
        for (int k = 0; k < 4; k++) acc[0][j][k] = 0.0f;

    gemm_run<64, 1>(ring, a0, a1, w0, w1, tx, acc);

    const int wid = tx >> 5, lane = tx & 31;
    const int mw = wid >> 1, nw = wid & 1;
    const int gr = lane >> 2, qc = (lane & 3) * 2;
#pragma unroll
    for (int jn = 0; jn < 3; jn++) {
        int ch = nq * BROWS + nw * 24 + jn * 8 + qc;
        float bv0 = bc[ch], bv1 = bc[ch + 1];
#pragma unroll
        for (int hf = 0; hf < 2; hf++) {
            int row = r0 + mw * 16 + gr + hf * 8;
            float c0 = tanhf(acc[0][jn][hf * 2 + 0] + bv0);
            float c1 = tanhf(acc[0][jn][hf * 2 + 1] + bv1);
            float2 g2 = *(const float2*)(g_gate + ((size_t)b * NL + row) * NC + ch);
            size_t sidx = ((size_t)b * PADL + row) * NC + ch;   // mem[row-1]
            bf162 sh2 = *(const bf162*)(cur0 + sidx);
            bf162 sl2 = *(const bf162*)(cur1 + sidx);
            float sh0 = __bfloat162float(sh2.x) + __bfloat162float(sl2.x);
            float sh1 = __bfloat162float(sh2.y) + __bfloat162float(sl2.y);
            float o0 = g2.x * sh0 + (1.0f - g2.x) * c0;
            float o1 = g2.y * sh1 + (1.0f - g2.y) * c1;
            size_t didx = ((size_t)b * PADL + row + 1) * NC + ch;
            bf162 hp, lp;
            split2(o0, o1, hp, lp);
            *(bf162*)(nxt0 + didx) = hp;
            *(bf162*)(nxt1 + didx) = lp;
            if (last) {
                float2 o;
                o.x = o0; o.y = o1;
                *(float2*)(outp + ((size_t)b * NL + row) * NC + ch) = o;
            }
        }
    }
}

// ---------------- prep kernels ----------------
__global__ void zero_kernel() {
    int idx = blockIdx.x * 256 + threadIdx.x;
    const int n4 = NB * PADL * NC / 8;
    if (idx < n4) {
        uint4 z = make_uint4(0, 0, 0, 0);
        ((uint4*)g_ma0)[idx] = z;
        ((uint4*)g_ma1)[idx] = z;
        ((uint4*)g_mb0)[idx] = z;
        ((uint4*)g_mb1)[idx] = z;
        ((uint4*)g_t0)[idx] = z;
        ((uint4*)g_t1)[idx] = z;
    }
}

__global__ void aprep_kernel(const float* __restrict__ x) {
    int idx = blockIdx.x * 256 + threadIdx.x;
    if (idx >= NB * NL * NC) return;
    int ch = idx % NC;
    int l = (idx / NC) % NL;
    int b = idx / (NC * NL);
    float v = x[idx];
    bf16 h = __float2bfloat16(v);
    bf16 lo = __float2bfloat16(v - __bfloat162float(h));
    size_t d = ((size_t)b * PADL + l + 1) * NC + ch;
    g_ma0[d] = h;
    g_ma1[d] = lo;
}

__global__ void wprep_kernel(const float* __restrict__ wr,
                             const float* __restrict__ wg,
                             const float* __restrict__ wc) {
    int idx = blockIdx.x * 256 + threadIdx.x;
    if (idx >= 3 * 3 * NC * NC) return;
    int co = idx % NC;
    int t = idx / NC;
    int ci = t % NC; t /= NC;
    int k = t % 3, c = t / 3;
    const float* w = (c == 0) ? wr : (c == 1) ? wg : wc;
    float v = w[((size_t)k * NC + ci) * NC + co];
    bf16 h = __float2bfloat16(v);
    bf16 lo = __float2bfloat16(v - __bfloat162float(h));
    size_t base = (size_t)k * NC + ci;
    g_wt[((size_t)(c * 2 + 0) * NC + co) * KTOT + base] = h;
    g_wt[((size_t)(c * 2 + 1) * NC + co) * KTOT + base] = lo;
}

extern "C" void kernel_launch(void* const* d_in, const int* in_sizes, int n_in,
                              void* d_out, int out_size) {
    const float* x  = (const float*)d_in[0];
    const float* wr = (const float*)d_in[1];
    const float* br = (const float*)d_in[2];
    const float* wg = (const float*)d_in[3];
    const float* bg = (const float*)d_in[4];
    const float* wc = (const float*)d_in[5];
    const float* bc = (const float*)d_in[6];
    float* out = (float*)d_out;

    bf16 *ma0, *ma1, *mb0, *mb1;
    cudaGetSymbolAddress((void**)&ma0, g_ma0);
    cudaGetSymbolAddress((void**)&ma1, g_ma1);
    cudaGetSymbolAddress((void**)&mb0, g_mb0);
    cudaGetSymbolAddress((void**)&mb1, g_mb1);

    const int RG_SMEM = 4 * (128 * 128 + BBYTES);    // 90112
    const int CD_SMEM = 4 * (64 * 128 + BBYTES);     // 57344
    cudaFuncSetAttribute(rg_kernel, cudaFuncAttributeMaxDynamicSharedMemorySize,
                         RG_SMEM);
    cudaFuncSetAttribute(cand_kernel, cudaFuncAttributeMaxDynamicSharedMemorySize,
                         CD_SMEM);

    zero_kernel<<<(NB * PADL * NC / 8 + 255) / 256, 256>>>();
    wprep_kernel<<<(3 * 3 * NC * NC + 255) / 256, 256>>>(wr, wg, wc);
    aprep_kernel<<<(NB * NL * NC + 255) / 256, 256>>>(x);

    for (int s = 0; s < NL; s++) {
        bf16* c0 = (s & 1) ? mb0 : ma0;
        bf16* c1 = (s & 1) ? mb1 : ma1;
        bf16* n0 = (s & 1) ? ma0 : mb0;
        bf16* n1 = (s & 1) ? ma1 : mb1;
        rg_kernel<<<256, 256, RG_SMEM>>>(c0, c1, br, bg);
        cand_kernel<<<256, 256, CD_SMEM>>>(c0, c1, n0, n1, bc, out,
                                           s == NL - 1 ? 1 : 0);
    }
}